// round 11
// baseline (speedup 1.0000x reference)
#include <cuda_runtime.h>
#include <math_constants.h>

#define N_SPAT 8000
#define CIN 64
#define DQK 8
#define DV 64
#define LOG2E_F 1.4426950408889634f
#define JSPLIT 2

typedef unsigned long long ull;

// ---------------- scratch (no allocations allowed) ----------------
__device__ float g_Q[2 * N_SPAT * DQK];             // [b][i][c8]
__device__ float g_K[2 * N_SPAT * DQK];             // [b][j][c8]
__device__ float g_V[2 * N_SPAT * DV];              // [b][j][c64] (tf32-rounded before attn)
__device__ float g_Opart[JSPLIT * 2 * N_SPAT * DV]; // [s][b][i][c]
__device__ float g_m[JSPLIT * 2 * N_SPAT];
__device__ float g_l[JSPLIT * 2 * N_SPAT];

// ---------------- f32x2 helpers (FFMA2 path, sm_10x) ----------------
__device__ __forceinline__ ull dup2(float x) {
    ull r;
    asm("mov.b64 %0, {%1, %1};" : "=l"(r) : "r"(__float_as_uint(x)));
    return r;
}
__device__ __forceinline__ ull pack2(float lo, float hi) {
    ull r;
    asm("mov.b64 %0, {%1, %2};" : "=l"(r) : "r"(__float_as_uint(lo)), "r"(__float_as_uint(hi)));
    return r;
}
__device__ __forceinline__ void fma2(ull& d, ull a, ull b) {
    asm("fma.rn.f32x2 %0, %1, %2, %0;" : "+l"(d) : "l"(a), "l"(b));
}
__device__ __forceinline__ float lo32(ull v) { return __uint_as_float((unsigned)v); }
__device__ __forceinline__ float hi32(ull v) { return __uint_as_float((unsigned)(v >> 32)); }

// ---------------- tf32 / mma helpers ----------------
__device__ __forceinline__ float to_tf32(float x) {
    unsigned r;
    asm("cvt.rna.tf32.f32 %0, %1;" : "=r"(r) : "f"(x));
    return __uint_as_float(r);
}
__device__ __forceinline__ void mma_tf32(float* c,
    unsigned a0, unsigned a1, unsigned a2, unsigned a3,
    unsigned b0, unsigned b1)
{
    asm volatile(
        "mma.sync.aligned.m16n8k8.row.col.f32.tf32.tf32.f32 "
        "{%0,%1,%2,%3},{%4,%5,%6,%7},{%8,%9},{%0,%1,%2,%3};"
        : "+f"(c[0]), "+f"(c[1]), "+f"(c[2]), "+f"(c[3])
        : "r"(a0), "r"(a1), "r"(a2), "r"(a3), "r"(b0), "r"(b1));
}

// ---------------- cp.async helpers ----------------
__device__ __forceinline__ void cp_async16(void* smem, const void* gmem) {
    unsigned saddr = (unsigned)__cvta_generic_to_shared(smem);
    asm volatile("cp.async.cg.shared.global [%0], [%1], 16;\n" :: "r"(saddr), "l"(gmem));
}
__device__ __forceinline__ void cp_commit() { asm volatile("cp.async.commit_group;\n"); }
__device__ __forceinline__ void cp_wait0() { asm volatile("cp.async.wait_group 0;\n"); }

// =====================================================================
// Conv kernel: fused Q/K/V 3x3x3 SAME conv.
// Grid (5 ocGroups, 40 = z*2+yhalf, 2 b), block 200 (proven shape).
// NEW thread decomposition: och = tid&1 (8 of the 16 oc), vg = tid>>1
// (an x-pair of voxels). Per (ic,dz,dy): a 4-float x-window serves both
// voxels for all 3 dx taps; weights via 2 LDS.128 per tap.
// Budget per (ic,dz,dy): 10 LDS wf vs 12 fma-cyc -> fma-bound.
// =====================================================================
#define CONV_T 200
#define ICCHUNK 8
#define PSY 12
#define PSX 22
#define PS (PSY * PSX)   // 264

__global__ __launch_bounds__(CONV_T) void conv_qkv_kernel(
    const float* __restrict__ x,
    const float* __restrict__ wq, const float* __restrict__ bq,
    const float* __restrict__ wk, const float* __restrict__ bk,
    const float* __restrict__ wv, const float* __restrict__ bv)
{
    __shared__ __align__(16) float slab[ICCHUNK][3][PS];
    __shared__ __align__(16) float wsm[ICCHUNK][27][16];

    const int g = blockIdx.x;
    const int z = blockIdx.y >> 1;
    const int yh = blockIdx.y & 1;
    const int b = blockIdx.z;
    const int tid = threadIdx.x;           // 0..199
    const int och = tid & 1;               // oc half (8 channels)
    const int vg  = tid >> 1;              // 0..99 voxel x-pair
    const int xp  = vg % 10;               // x-pair -> x = 2xp, 2xp+1
    const int yrow = vg / 10;              // 0..9
    const int yg = yh * 10 + yrow;
    const int ocb = g * 16 + och * 8;      // first oc of this thread

    ull acc0[4], acc1[4];                  // [pair] for voxel0 / voxel1
#pragma unroll
    for (int p = 0; p < 4; ++p) {
        int oc0 = ocb + 2 * p, oc1 = oc0 + 1;
        float b0 = (oc0 < 8) ? bq[oc0] : (oc0 < 16 ? bk[oc0 - 8] : bv[oc0 - 16]);
        float b1 = (oc1 < 8) ? bq[oc1] : (oc1 < 16 ? bk[oc1 - 8] : bv[oc1 - 16]);
        acc0[p] = pack2(b0, b1);
        acc1[p] = acc0[p];
    }

    for (int chunk = 0; chunk < CIN / ICCHUNK; ++chunk) {
        __syncthreads();
        // fill padded input slab (zero borders): rows yh*10-1 .. +10
        for (int idx = tid; idx < ICCHUNK * 3 * PS; idx += CONV_T) {
            int spl = idx % PS;
            int zz = (idx / PS) % 3;
            int ic = idx / (3 * PS);
            int yy = yh * 10 + spl / PSX - 1;
            int xx = spl % PSX - 1;
            int zg = z + zz - 1;
            float v = 0.f;
            if ((unsigned)zg < 20u && (unsigned)yy < 20u && (unsigned)xx < 20u)
                v = x[(((size_t)b * 64 + chunk * ICCHUNK + ic) * 20 + zg) * 400 + yy * 20 + xx];
            slab[ic][zz][spl] = v;
        }
        // fill weights [ic][tap][ocl]  (oc pairs contiguous for f32x2)
        for (int idx = tid; idx < ICCHUNK * 27 * 16; idx += CONV_T) {
            int ocl = idx & 15;
            int tap = (idx >> 4) % 27;
            int ic = idx / (27 * 16);
            int oc = g * 16 + ocl;
            int icg = chunk * ICCHUNK + ic;
            float w;
            if (oc < 8)       w = wq[((size_t)oc * 64 + icg) * 27 + tap];
            else if (oc < 16) w = wk[((size_t)(oc - 8) * 64 + icg) * 27 + tap];
            else              w = wv[((size_t)(oc - 16) * 64 + icg) * 27 + tap];
            wsm[ic][tap][ocl] = w;
        }
        __syncthreads();

#pragma unroll 2
        for (int ic = 0; ic < ICCHUNK; ++ic) {
#pragma unroll
            for (int dz = 0; dz < 3; ++dz) {
#pragma unroll
                for (int dy = 0; dy < 3; ++dy) {
                    const float* row = &slab[ic][dz][(yrow + dy) * PSX + 2 * xp];
                    ull win[4];
#pragma unroll
                    for (int e = 0; e < 4; ++e) win[e] = dup2(row[e]);
#pragma unroll
                    for (int dx = 0; dx < 3; ++dx) {
                        const ulonglong2* wp =
                            (const ulonglong2*)&wsm[ic][dz * 9 + dy * 3 + dx][och * 8];
                        ulonglong2 wA = wp[0], wB = wp[1];   // 4 weight pairs
                        ull w0 = win[dx], w1 = win[dx + 1];
                        fma2(acc0[0], wA.x, w0);
                        fma2(acc0[1], wA.y, w0);
                        fma2(acc0[2], wB.x, w0);
                        fma2(acc0[3], wB.y, w0);
                        fma2(acc1[0], wA.x, w1);
                        fma2(acc1[1], wA.y, w1);
                        fma2(acc1[2], wB.x, w1);
                        fma2(acc1[3], wB.y, w1);
                    }
                }
            }
        }
    }

    // stores: thread owns 8 consecutive channels for 2 voxels
    const int ibase = z * 400 + yg * 20 + 2 * xp;
#pragma unroll
    for (int v = 0; v < 2; ++v) {
        ull* a = v ? acc1 : acc0;
        int i = ibase + v;
        float4 f0 = make_float4(lo32(a[0]), hi32(a[0]), lo32(a[1]), hi32(a[1]));
        float4 f1 = make_float4(lo32(a[2]), hi32(a[2]), lo32(a[3]), hi32(a[3]));
        if (g == 0) {
            float* base = (och == 0) ? g_Q : g_K;
            float4* d = (float4*)(base + ((size_t)b * N_SPAT + i) * DQK);
            d[0] = f0; d[1] = f1;
        } else {
            float4* d = (float4*)(g_V + ((size_t)b * N_SPAT + i) * DV + (g - 1) * 16 + och * 8);
            d[0] = f0; d[1] = f1;
        }
    }
}

// =====================================================================
// Round V to tf32 in place (PV GEMM runs in tf32; Q/K stay f32).
// =====================================================================
__global__ __launch_bounds__(256) void roundv_kernel()
{
    int idx = blockIdx.x * 256 + threadIdx.x;
    if (idx < 2 * N_SPAT * DV) g_V[idx] = to_tf32(g_V[idx]);
}

// =====================================================================
// Flash attention (split-KV partials), tensor-core PV.
// BM=64 rows/CTA, 128 threads (4 warps), grid (125, 2, JSPLIT)=500 CTAs.
// Phase A: scalar f32 QK^T, 4x8 micro-tile (tr=tid>>3 in 0..15, tc=tid&7).
// Softmax: octet-shuffle; P tf32 -> sP[64][68] (warp-local rows).
// Phase C: mma.m16n8k8.tf32; warp w owns mtile rows 16w..16w+15
//   (produced by the same warp -> __syncwarp suffices).
// Dyn smem identical to R10: 58624 B -> 3 CTAs/SM = 12 warps/SM.
// =====================================================================
#define BM 64
#define BN 64
#define ATT_T 128
#define VPAD 68
#define ATT_SMEM_BYTES (14656 * 4)

__global__ __launch_bounds__(ATT_T) void attn_kernel()
{
    extern __shared__ __align__(16) float dyn[];
    float* sQT = dyn;              // [8][64]
    float* sKT = dyn + 512;        // [2][8][64]
    float* sV  = dyn + 1536;       // [2][64][VPAD]
    float* sP  = dyn + 10240;      // [64][VPAD]
    float* sAl = dyn + 14592;      // [64]

    const int b = blockIdx.y;
    const int sp = blockIdx.z;
    const int i0 = blockIdx.x * BM;
    const int tid = threadIdx.x;
    const int tc = tid & 7;
    const int tr = tid >> 3;          // 0..15, rows 4tr..4tr+3
    const int w = tid >> 5;           // warp 0..3 -> mtile rows 16w..16w+15
    const int lane = tid & 31;
    const int g4 = lane >> 2;         // mma groupID 0..7
    const int q4 = lane & 3;          // mma tid-in-group

    const int NT = N_SPAT / BN;       // 125
    const int t0 = (sp * NT) / JSPLIT;
    const int t1 = ((sp + 1) * NT) / JSPLIT;

    const float* Qb = g_Q + (size_t)b * N_SPAT * DQK;
    const float* Kb = g_K + (size_t)b * N_SPAT * DQK;
    const float* Vb = g_V + (size_t)b * N_SPAT * DV;

    // ---- load Q tile, transpose, pre-scale by log2(e) ----
    {
        int il = tid >> 1, half = tid & 1;
        float4 q = *(const float4*)(Qb + (size_t)(i0 + il) * DQK + half * 4);
        sQT[(half * 4 + 0) * 64 + il] = q.x * LOG2E_F;
        sQT[(half * 4 + 1) * 64 + il] = q.y * LOG2E_F;
        sQT[(half * 4 + 2) * 64 + il] = q.z * LOG2E_F;
        sQT[(half * 4 + 3) * 64 + il] = q.w * LOG2E_F;
    }

    float m[4], l[4];
    float o[8][4];                    // [ntile][c0..c3] mma accumulators
#pragma unroll
    for (int ii = 0; ii < 4; ++ii) { m[ii] = -CUDART_INF_F; l[ii] = 0.f; }
#pragma unroll
    for (int nt = 0; nt < 8; ++nt)
#pragma unroll
        for (int e = 0; e < 4; ++e) o[nt][e] = 0.f;

    // ---- prologue: stage tile t0 into buffer 0 ----
    {
        const float* ksrc = Kb + (size_t)t0 * BN * DQK;
        float4 kreg = ((const float4*)ksrc)[tid];
        const float* vsrc = Vb + (size_t)t0 * BN * DV;
#pragma unroll
        for (int q = 0; q < 8; ++q) {
            int ch = tid + q * 128;          // 0..1023
            int row = ch >> 4, off = ch & 15;
            cp_async16(&sV[row * VPAD + off * 4], vsrc + row * 64 + off * 4);
        }
        cp_commit();
        int j = tid >> 1, k0 = (tid & 1) * 4;
        sKT[(k0 + 0) * 64 + j] = kreg.x; sKT[(k0 + 1) * 64 + j] = kreg.y;
        sKT[(k0 + 2) * 64 + j] = kreg.z; sKT[(k0 + 3) * 64 + j] = kreg.w;
        cp_wait0();
        __syncthreads();
    }

    for (int it = t0; it < t1; ++it) {
        const int cur = (it - t0) & 1;
        const int nxt = cur ^ 1;
        const bool pref = (it + 1 < t1);
        float4 kreg;
        if (pref) {
            const float* ksrc = Kb + (size_t)(it + 1) * BN * DQK;
            kreg = ((const float4*)ksrc)[tid];
            const float* vsrc = Vb + (size_t)(it + 1) * BN * DV;
#pragma unroll
            for (int q = 0; q < 8; ++q) {
                int ch = tid + q * 128;
                int row = ch >> 4, off = ch & 15;
                cp_async16(&sV[nxt * 64 * VPAD + row * VPAD + off * 4],
                           vsrc + row * 64 + off * 4);
            }
            cp_commit();
        }

        // ---- phase A: S = Q K^T (scalar f32, 4x8 micro-tile) ----
        float s[4][8];
#pragma unroll
        for (int ii = 0; ii < 4; ++ii)
#pragma unroll
            for (int jj = 0; jj < 8; ++jj) s[ii][jj] = 0.f;

#pragma unroll
        for (int k = 0; k < DQK; ++k) {
            float4 q = *(const float4*)&sQT[k * 64 + 4 * tr];
            float4 ka = *(const float4*)&sKT[cur * 512 + k * 64 + 8 * tc];
            float4 kb = *(const float4*)&sKT[cur * 512 + k * 64 + 8 * tc + 4];
            float qv[4] = {q.x, q.y, q.z, q.w};
            float kv[8] = {ka.x, ka.y, ka.z, ka.w, kb.x, kb.y, kb.z, kb.w};
#pragma unroll
            for (int ii = 0; ii < 4; ++ii)
#pragma unroll
                for (int jj = 0; jj < 8; ++jj)
                    s[ii][jj] = fmaf(qv[ii], kv[jj], s[ii][jj]);
        }

        // ---- online softmax (base-2), publish tf32 P + alpha ----
#pragma unroll
        for (int ii = 0; ii < 4; ++ii) {
            float mx = s[ii][0];
#pragma unroll
            for (int jj = 1; jj < 8; ++jj) mx = fmaxf(mx, s[ii][jj]);
            mx = fmaxf(mx, __shfl_xor_sync(0xffffffffu, mx, 1));
            mx = fmaxf(mx, __shfl_xor_sync(0xffffffffu, mx, 2));
            mx = fmaxf(mx, __shfl_xor_sync(0xffffffffu, mx, 4));
            float mnew = fmaxf(m[ii], mx);
            float alpha = exp2f(m[ii] - mnew);
            m[ii] = mnew;
            float rs = 0.f;
            float pr[8];
#pragma unroll
            for (int jj = 0; jj < 8; ++jj) {
                float p = exp2f(s[ii][jj] - mnew);
                rs += p;
                pr[jj] = to_tf32(p);
            }
            rs += __shfl_xor_sync(0xffffffffu, rs, 1);
            rs += __shfl_xor_sync(0xffffffffu, rs, 2);
            rs += __shfl_xor_sync(0xffffffffu, rs, 4);
            l[ii] = l[ii] * alpha + rs;
            if (tc == 0) sAl[4 * tr + ii] = alpha;
            float* prow = &sP[(4 * tr + ii) * VPAD + 8 * tc];
            *(float4*)prow       = make_float4(pr[0], pr[1], pr[2], pr[3]);
            *(float4*)(prow + 4) = make_float4(pr[4], pr[5], pr[6], pr[7]);
        }
        __syncwarp();    // P/alpha rows are produced & consumed within the warp

        // ---- rescale O fragments by alpha ----
        {
            float al = sAl[16 * w + g4];
            float ah = sAl[16 * w + 8 + g4];
#pragma unroll
            for (int nt = 0; nt < 8; ++nt) {
                o[nt][0] *= al; o[nt][1] *= al;
                o[nt][2] *= ah; o[nt][3] *= ah;
            }
        }

        // ---- phase C: O += P @ V via mma.tf32 ----
        {
            const float* vb = sV + cur * 64 * VPAD;
#pragma unroll
            for (int ks = 0; ks < 8; ++ks) {
                int row0 = 16 * w + g4;
                unsigned a0 = __float_as_uint(sP[row0 * VPAD + 8 * ks + q4]);
                unsigned a1 = __float_as_uint(sP[(row0 + 8) * VPAD + 8 * ks + q4]);
                unsigned a2 = __float_as_uint(sP[row0 * VPAD + 8 * ks + q4 + 4]);
                unsigned a3 = __float_as_uint(sP[(row0 + 8) * VPAD + 8 * ks + q4 + 4]);
#pragma unroll
                for (int nt = 0; nt < 8; ++nt) {
                    unsigned b0 = __float_as_uint(vb[(8 * ks + q4) * VPAD + 8 * nt + g4]);
                    unsigned b1 = __float_as_uint(vb[(8 * ks + q4 + 4) * VPAD + 8 * nt + g4]);
                    mma_tf32(o[nt], a0, a1, a2, a3, b0, b1);
                }
            }
        }

        if (pref) {
            float* kt = &sKT[nxt * 512];
            int j = tid >> 1, k0 = (tid & 1) * 4;
            kt[(k0 + 0) * 64 + j] = kreg.x; kt[(k0 + 1) * 64 + j] = kreg.y;
            kt[(k0 + 2) * 64 + j] = kreg.z; kt[(k0 + 3) * 64 + j] = kreg.w;
        }
        cp_wait0();
        __syncthreads();
    }

    // ---- epilogue: partials (fragment layout) + m/l (scalar layout) ----
    const size_t sb = (size_t)(sp * 2 + b);
    {
        int R = i0 + 16 * w + g4;
#pragma unroll
        for (int nt = 0; nt < 8; ++nt) {
            float2* d0 = (float2*)(g_Opart + (sb * N_SPAT + R) * DV + 8 * nt + 2 * q4);
            *d0 = make_float2(o[nt][0], o[nt][1]);
            float2* d1 = (float2*)(g_Opart + (sb * N_SPAT + R + 8) * DV + 8 * nt + 2 * q4);
            *d1 = make_float2(o[nt][2], o[nt][3]);
        }
    }
    if (tc == 0) {
#pragma unroll
        for (int ii = 0; ii < 4; ++ii) {
            int i = i0 + 4 * tr + ii;
            g_m[sb * N_SPAT + i] = m[ii];
            g_l[sb * N_SPAT + i] = l[ii];
        }
    }
}

// =====================================================================
// Merge kernel: combine JSPLIT partials (log-sum-exp, base-2 domain),
// transpose via smem, coalesced out[b][c][i] writes.
// =====================================================================
__global__ __launch_bounds__(256) void merge_kernel(float* __restrict__ out)
{
    __shared__ float T[DV][65];   // [c][i_local]

    const int b = blockIdx.y;
    const int i0 = blockIdx.x * 64;
    const int tid = threadIdx.x;
    const int il = tid >> 2;          // 0..63
    const int cq = tid & 3;           // channel quad group
    const int i = i0 + il;

    float mm[JSPLIT], coef[JSPLIT];
    float mstar = -CUDART_INF_F;
#pragma unroll
    for (int s = 0; s < JSPLIT; ++s) {
        mm[s] = g_m[((size_t)(s * 2 + b)) * N_SPAT + i];
        mstar = fmaxf(mstar, mm[s]);
    }
    float denom = 0.f;
#pragma unroll
    for (int s = 0; s < JSPLIT; ++s) {
        coef[s] = exp2f(mm[s] - mstar);
        denom += coef[s] * g_l[((size_t)(s * 2 + b)) * N_SPAT + i];
    }
    const float inv = 1.0f / denom;

    float acc[16];
#pragma unroll
    for (int e = 0; e < 16; ++e) acc[e] = 0.f;
#pragma unroll
    for (int s = 0; s < JSPLIT; ++s) {
        const float4* src = (const float4*)(g_Opart +
            (((size_t)(s * 2 + b)) * N_SPAT + i) * DV + cq * 16);
        float c = coef[s];
#pragma unroll
        for (int q = 0; q < 4; ++q) {
            float4 f = src[q];
            acc[4 * q + 0] = fmaf(c, f.x, acc[4 * q + 0]);
            acc[4 * q + 1] = fmaf(c, f.y, acc[4 * q + 1]);
            acc[4 * q + 2] = fmaf(c, f.z, acc[4 * q + 2]);
            acc[4 * q + 3] = fmaf(c, f.w, acc[4 * q + 3]);
        }
    }
#pragma unroll
    for (int e = 0; e < 16; ++e) T[cq * 16 + e][il] = acc[e] * inv;
    __syncthreads();

    {
        const int c = tid >> 2;
        const int ich = (tid & 3) * 16;
        float* dst = out + ((size_t)b * DV + c) * N_SPAT + i0 + ich;
#pragma unroll
        for (int q = 0; q < 4; ++q)
            ((float4*)dst)[q] = make_float4(T[c][ich + 4 * q + 0], T[c][ich + 4 * q + 1],
                                            T[c][ich + 4 * q + 2], T[c][ich + 4 * q + 3]);
    }
}

// =====================================================================
extern "C" void kernel_launch(void* const* d_in, const int* in_sizes, int n_in,
                              void* d_out, int out_size)
{
    const float* x  = (const float*)d_in[0];
    const float* wq = (const float*)d_in[1];
    const float* bq = (const float*)d_in[2];
    const float* wk = (const float*)d_in[3];
    const float* bk = (const float*)d_in[4];
    const float* wv = (const float*)d_in[5];
    const float* bv = (const float*)d_in[6];
    float* out = (float*)d_out;

    cudaFuncSetAttribute(attn_kernel,
                         cudaFuncAttributeMaxDynamicSharedMemorySize,
                         ATT_SMEM_BYTES);

    dim3 cgrid(5, 40, 2);                 // ocGroup, z*2+yhalf, batch
    conv_qkv_kernel<<<cgrid, CONV_T>>>(x, wq, bq, wk, bk, wv, bv);

    roundv_kernel<<<(2 * N_SPAT * DV + 255) / 256, 256>>>();

    dim3 agrid(N_SPAT / BM, 2, JSPLIT);   // 125 x 2 x 2 = 500 CTAs
    attn_kernel<<<agrid, ATT_T, ATT_SMEM_BYTES>>>();

    dim3 mgrid(N_SPAT / 64, 2);
    merge_kernel<<<mgrid, 256>>>(out);
}

// round 13
// speedup vs baseline: 1.1461x; 1.1461x over previous
#include <cuda_runtime.h>
#include <math_constants.h>

#define N_SPAT 8000
#define CIN 64
#define DQK 8
#define DV 64
#define LOG2E_F 1.4426950408889634f
#define JSPLIT 2

typedef unsigned long long ull;

// ---------------- scratch (no allocations allowed) ----------------
__device__ float g_Q[2 * N_SPAT * DQK];             // hi part (scaled+tf32)
__device__ float g_Qlo[2 * N_SPAT * DQK];           // lo residual (tf32)
__device__ float g_K[2 * N_SPAT * DQK];             // hi part (tf32)
__device__ float g_Klo[2 * N_SPAT * DQK];           // lo residual (tf32)
__device__ float g_V[2 * N_SPAT * DV];              // tf32-rounded
__device__ float g_Opart[JSPLIT * 2 * N_SPAT * DV]; // [s][b][i][c]
__device__ float g_m[JSPLIT * 2 * N_SPAT];
__device__ float g_l[JSPLIT * 2 * N_SPAT];

// ---------------- f32x2 helpers (FFMA2 path, sm_10x) ----------------
__device__ __forceinline__ ull dup2(float x) {
    ull r;
    asm("mov.b64 %0, {%1, %1};" : "=l"(r) : "r"(__float_as_uint(x)));
    return r;
}
__device__ __forceinline__ ull pack2(float lo, float hi) {
    ull r;
    asm("mov.b64 %0, {%1, %2};" : "=l"(r) : "r"(__float_as_uint(lo)), "r"(__float_as_uint(hi)));
    return r;
}
__device__ __forceinline__ void fma2(ull& d, ull a, ull b) {
    asm("fma.rn.f32x2 %0, %1, %2, %0;" : "+l"(d) : "l"(a), "l"(b));
}
__device__ __forceinline__ float lo32(ull v) { return __uint_as_float((unsigned)v); }
__device__ __forceinline__ float hi32(ull v) { return __uint_as_float((unsigned)(v >> 32)); }

// ---------------- tf32 / mma helpers ----------------
__device__ __forceinline__ float to_tf32(float x) {
    unsigned r;
    asm("cvt.rna.tf32.f32 %0, %1;" : "=r"(r) : "f"(x));
    return __uint_as_float(r);
}
// D = A*B + D
__device__ __forceinline__ void mma_tf32(float* c,
    float a0, float a1, float a2, float a3, float b0, float b1)
{
    asm volatile(
        "mma.sync.aligned.m16n8k8.row.col.f32.tf32.tf32.f32 "
        "{%0,%1,%2,%3},{%4,%5,%6,%7},{%8,%9},{%0,%1,%2,%3};"
        : "+f"(c[0]), "+f"(c[1]), "+f"(c[2]), "+f"(c[3])
        : "r"(__float_as_uint(a0)), "r"(__float_as_uint(a1)),
          "r"(__float_as_uint(a2)), "r"(__float_as_uint(a3)),
          "r"(__float_as_uint(b0)), "r"(__float_as_uint(b1)));
}
// D = A*B  (C = 0)
__device__ __forceinline__ void mma_tf32_z(float* d,
    float a0, float a1, float a2, float a3, float b0, float b1)
{
    asm volatile(
        "mma.sync.aligned.m16n8k8.row.col.f32.tf32.tf32.f32 "
        "{%0,%1,%2,%3},{%4,%5,%6,%7},{%8,%9},{%10,%10,%10,%10};"
        : "=f"(d[0]), "=f"(d[1]), "=f"(d[2]), "=f"(d[3])
        : "r"(__float_as_uint(a0)), "r"(__float_as_uint(a1)),
          "r"(__float_as_uint(a2)), "r"(__float_as_uint(a3)),
          "r"(__float_as_uint(b0)), "r"(__float_as_uint(b1)), "f"(0.f));
}

// ---------------- cp.async helpers ----------------
__device__ __forceinline__ void cp_async16(void* smem, const void* gmem) {
    unsigned saddr = (unsigned)__cvta_generic_to_shared(smem);
    asm volatile("cp.async.cg.shared.global [%0], [%1], 16;\n" :: "r"(saddr), "l"(gmem));
}
__device__ __forceinline__ void cp_commit() { asm volatile("cp.async.commit_group;\n"); }
__device__ __forceinline__ void cp_wait0() { asm volatile("cp.async.wait_group 0;\n"); }

// =====================================================================
// Conv kernel (R5, proven ~268us): fused Q/K/V 3x3x3 SAME conv.
// Grid (5 ocGroups, 40 = z*2+yhalf, 2 b), block 200.
// =====================================================================
#define CONV_T 200
#define ICCHUNK 8
#define PSY 12
#define PSX 22
#define PS (PSY * PSX)   // 264

__global__ __launch_bounds__(CONV_T) void conv_qkv_kernel(
    const float* __restrict__ x,
    const float* __restrict__ wq, const float* __restrict__ bq,
    const float* __restrict__ wk, const float* __restrict__ bk,
    const float* __restrict__ wv, const float* __restrict__ bv)
{
    __shared__ __align__(16) float slab[ICCHUNK][3][PS];
    __shared__ __align__(16) float wsm[ICCHUNK][27][16];

    const int g = blockIdx.x;
    const int z = blockIdx.y >> 1;
    const int yh = blockIdx.y & 1;
    const int b = blockIdx.z;
    const int tid = threadIdx.x;           // 0..199
    const int yl = tid / 20;               // 0..9
    const int xc = tid % 20;
    const int yg = yh * 10 + yl;
    const int ocbase = g * 16;

    ull acc[8];
#pragma unroll
    for (int o2 = 0; o2 < 8; ++o2) {
        int oc0 = ocbase + 2 * o2, oc1 = oc0 + 1;
        float b0 = (oc0 < 8) ? bq[oc0] : (oc0 < 16 ? bk[oc0 - 8] : bv[oc0 - 16]);
        float b1 = (oc1 < 8) ? bq[oc1] : (oc1 < 16 ? bk[oc1 - 8] : bv[oc1 - 16]);
        acc[o2] = pack2(b0, b1);
    }

    for (int chunk = 0; chunk < CIN / ICCHUNK; ++chunk) {
        __syncthreads();
        for (int idx = tid; idx < ICCHUNK * 3 * PS; idx += CONV_T) {
            int spl = idx % PS;
            int zz = (idx / PS) % 3;
            int ic = idx / (3 * PS);
            int yy = yh * 10 + spl / PSX - 1;
            int xx = spl % PSX - 1;
            int zg = z + zz - 1;
            float v = 0.f;
            if ((unsigned)zg < 20u && (unsigned)yy < 20u && (unsigned)xx < 20u)
                v = x[(((size_t)b * 64 + chunk * ICCHUNK + ic) * 20 + zg) * 400 + yy * 20 + xx];
            slab[ic][zz][spl] = v;
        }
        for (int idx = tid; idx < ICCHUNK * 27 * 16; idx += CONV_T) {
            int ocl = idx & 15;
            int tap = (idx >> 4) % 27;
            int ic = idx / (27 * 16);
            int oc = ocbase + ocl;
            int icg = chunk * ICCHUNK + ic;
            float w;
            if (oc < 8)       w = wq[((size_t)oc * 64 + icg) * 27 + tap];
            else if (oc < 16) w = wk[((size_t)(oc - 8) * 64 + icg) * 27 + tap];
            else              w = wv[((size_t)(oc - 16) * 64 + icg) * 27 + tap];
            wsm[ic][tap][ocl] = w;
        }
        __syncthreads();

#pragma unroll 2
        for (int ic = 0; ic < ICCHUNK; ++ic) {
#pragma unroll
            for (int dz = 0; dz < 3; ++dz) {
                const float* sl = &slab[ic][dz][yl * PSX + xc];
#pragma unroll
                for (int t9 = 0; t9 < 9; ++t9) {
                    const int dy = t9 / 3, dx = t9 % 3;
                    ull xd = dup2(sl[dy * PSX + dx]);
                    const ull* wp = (const ull*)&wsm[ic][dz * 9 + t9][0];
#pragma unroll
                    for (int o2 = 0; o2 < 8; ++o2) fma2(acc[o2], wp[o2], xd);
                }
            }
        }
    }

    const int i = z * 400 + yg * 20 + xc;
    if (g == 0) {
        float4* qd = (float4*)(g_Q + ((size_t)b * N_SPAT + i) * DQK);
        qd[0] = make_float4(lo32(acc[0]), hi32(acc[0]), lo32(acc[1]), hi32(acc[1]));
        qd[1] = make_float4(lo32(acc[2]), hi32(acc[2]), lo32(acc[3]), hi32(acc[3]));
        float4* kd = (float4*)(g_K + ((size_t)b * N_SPAT + i) * DQK);
        kd[0] = make_float4(lo32(acc[4]), hi32(acc[4]), lo32(acc[5]), hi32(acc[5]));
        kd[1] = make_float4(lo32(acc[6]), hi32(acc[6]), lo32(acc[7]), hi32(acc[7]));
    } else {
        float4* vd = (float4*)(g_V + ((size_t)b * N_SPAT + i) * DV + (g - 1) * 16);
#pragma unroll
        for (int q = 0; q < 4; ++q)
            vd[q] = make_float4(lo32(acc[2 * q]), hi32(acc[2 * q]),
                                lo32(acc[2 * q + 1]), hi32(acc[2 * q + 1]));
    }
}

// =====================================================================
// Round: V -> tf32; Q (scaled by log2e) and K -> hi/lo tf32 split.
// =====================================================================
#define NV_ELEM (2 * N_SPAT * DV)
#define NQ_ELEM (2 * N_SPAT * DQK)

__global__ __launch_bounds__(256) void round_all_kernel()
{
    int idx = blockIdx.x * 256 + threadIdx.x;
    if (idx < NV_ELEM) {
        g_V[idx] = to_tf32(g_V[idx]);
    } else if (idx < NV_ELEM + NQ_ELEM) {
        int j = idx - NV_ELEM;
        float qs = g_Q[j] * LOG2E_F;
        float hi = to_tf32(qs);
        g_Q[j] = hi;
        g_Qlo[j] = to_tf32(qs - hi);
    } else if (idx < NV_ELEM + 2 * NQ_ELEM) {
        int j = idx - NV_ELEM - NQ_ELEM;
        float k = g_K[j];
        float hi = to_tf32(k);
        g_K[j] = hi;
        g_Klo[j] = to_tf32(k - hi);
    }
}

// =====================================================================
// Flash attention (split-KV partials), ALL-mma with 3xTF32 exact QK.
// BM=64 rows/CTA, 128 threads (4 warps; warp w owns rows 16w..16w+15),
// grid (125, 2, JSPLIT) = 500 CTAs.
// Phase A: S = Qhi*Khi + Qhi*Klo + Qlo*Khi via mma (near-fp32 scores).
// Softmax on S fragments; P stays register-resident (tf32).
// Phase C: C->A fragment permute via 8 shfl + 4 sel per k-slab, mma PV.
// Static smem: sKh+sKl 2*2*64*12*4 = 12288 + sV 2*64*72*4 = 36864
//   -> 49152 B -> 4 CTAs/SM.
// =====================================================================
#define BM 64
#define BN 64
#define ATT_T 128
#define KPAD 12
#define VPAD 72

__global__ __launch_bounds__(ATT_T, 4) void attn_kernel()
{
    __shared__ __align__(16) float sKh[2][BN * KPAD];
    __shared__ __align__(16) float sKl[2][BN * KPAD];
    __shared__ __align__(16) float sV[2][BN * VPAD];

    const int b = blockIdx.y;
    const int sp = blockIdx.z;
    const int i0 = blockIdx.x * BM;
    const int tid = threadIdx.x;
    const int w = tid >> 5;           // warp 0..3 -> rows 16w..16w+15
    const int lane = tid & 31;
    const int g4 = lane >> 2;         // mma groupID 0..7
    const int q4 = lane & 3;          // mma tid-in-group

    const int NT = N_SPAT / BN;       // 125
    const int t0 = (sp * NT) / JSPLIT;
    const int t1 = ((sp + 1) * NT) / JSPLIT;

    const float* Qb  = g_Q   + (size_t)b * N_SPAT * DQK;
    const float* Qlb = g_Qlo + (size_t)b * N_SPAT * DQK;
    const float* Kb  = g_K   + (size_t)b * N_SPAT * DQK;
    const float* Klb = g_Klo + (size_t)b * N_SPAT * DQK;
    const float* Vb  = g_V   + (size_t)b * N_SPAT * DV;

    // ---- loop-invariant Q A-fragments (hi + lo) ----
    const int r0 = i0 + 16 * w + g4;
    const int r1 = r0 + 8;
    const float ah0 = Qb[r0 * DQK + q4];
    const float ah1 = Qb[r1 * DQK + q4];
    const float ah2 = Qb[r0 * DQK + q4 + 4];
    const float ah3 = Qb[r1 * DQK + q4 + 4];
    const float al0 = Qlb[r0 * DQK + q4];
    const float al1 = Qlb[r1 * DQK + q4];
    const float al2 = Qlb[r0 * DQK + q4 + 4];
    const float al3 = Qlb[r1 * DQK + q4 + 4];

    float m0 = -CUDART_INF_F, m1 = -CUDART_INF_F, l0 = 0.f, l1 = 0.f;
    float o[8][4];
#pragma unroll
    for (int nt = 0; nt < 8; ++nt)
#pragma unroll
        for (int e = 0; e < 4; ++e) o[nt][e] = 0.f;

    const int jj = tid >> 1, hh = tid & 1;   // K staging coords

    // ---- prologue: stage tile t0 into buffer 0 ----
    {
        float4 kh = ((const float4*)(Kb + (size_t)t0 * BN * DQK))[tid];
        float4 kl = ((const float4*)(Klb + (size_t)t0 * BN * DQK))[tid];
        const float* vsrc = Vb + (size_t)t0 * BN * DV;
#pragma unroll
        for (int q = 0; q < 8; ++q) {
            int ch = tid + q * 128;
            int row = ch >> 4, off = ch & 15;
            cp_async16(&sV[0][row * VPAD + off * 4], vsrc + row * 64 + off * 4);
        }
        cp_commit();
        *(float4*)&sKh[0][jj * KPAD + hh * 4] = kh;
        *(float4*)&sKl[0][jj * KPAD + hh * 4] = kl;
        cp_wait0();
        __syncthreads();
    }

    const int srcA = (g4 << 2) + (q4 >> 1);   // lane holding col q4 (regs c0/c1)
    const int srcB = srcA + 2;                // lane holding col q4+4
    const bool oddq = (q4 & 1);

    for (int it = t0; it < t1; ++it) {
        const int cur = (it - t0) & 1;
        const int nxt = cur ^ 1;
        const bool pref = (it + 1 < t1);
        float4 khr, klr;
        if (pref) {
            khr = ((const float4*)(Kb + (size_t)(it + 1) * BN * DQK))[tid];
            klr = ((const float4*)(Klb + (size_t)(it + 1) * BN * DQK))[tid];
            const float* vsrc = Vb + (size_t)(it + 1) * BN * DV;
#pragma unroll
            for (int q = 0; q < 8; ++q) {
                int ch = tid + q * 128;
                int row = ch >> 4, off = ch & 15;
                cp_async16(&sV[nxt][row * VPAD + off * 4], vsrc + row * 64 + off * 4);
            }
            cp_commit();
        }

        // ---- phase A: S via 3xTF32 mma (near-fp32 accuracy) ----
        float s[8][4];
        {
            const float* kbh = sKh[cur];
            const float* kbl = sKl[cur];
#pragma unroll
            for (int nt = 0; nt < 8; ++nt) {
                float b0h = kbh[(8 * nt + g4) * KPAD + q4];
                float b1h = kbh[(8 * nt + g4) * KPAD + q4 + 4];
                float b0l = kbl[(8 * nt + g4) * KPAD + q4];
                float b1l = kbl[(8 * nt + g4) * KPAD + q4 + 4];
                mma_tf32_z(s[nt], ah0, ah1, ah2, ah3, b0h, b1h);
                mma_tf32 (s[nt], ah0, ah1, ah2, ah3, b0l, b1l);
                mma_tf32 (s[nt], al0, al1, al2, al3, b0h, b1h);
            }
        }

        // ---- softmax on fragments (rows r0: c0,c1; r1: c2,c3) ----
        {
            float mx0 = fmaxf(s[0][0], s[0][1]);
            float mx1 = fmaxf(s[0][2], s[0][3]);
#pragma unroll
            for (int nt = 1; nt < 8; ++nt) {
                mx0 = fmaxf(mx0, fmaxf(s[nt][0], s[nt][1]));
                mx1 = fmaxf(mx1, fmaxf(s[nt][2], s[nt][3]));
            }
            mx0 = fmaxf(mx0, __shfl_xor_sync(0xffffffffu, mx0, 1));
            mx0 = fmaxf(mx0, __shfl_xor_sync(0xffffffffu, mx0, 2));
            mx1 = fmaxf(mx1, __shfl_xor_sync(0xffffffffu, mx1, 1));
            mx1 = fmaxf(mx1, __shfl_xor_sync(0xffffffffu, mx1, 2));
            float m0n = fmaxf(m0, mx0);
            float m1n = fmaxf(m1, mx1);
            float alpha0 = exp2f(m0 - m0n);
            float alpha1 = exp2f(m1 - m1n);
            m0 = m0n; m1 = m1n;
            float rs0 = 0.f, rs1 = 0.f;
#pragma unroll
            for (int nt = 0; nt < 8; ++nt) {
                float p0 = exp2f(s[nt][0] - m0);
                float p1 = exp2f(s[nt][1] - m0);
                float p2 = exp2f(s[nt][2] - m1);
                float p3 = exp2f(s[nt][3] - m1);
                rs0 += p0 + p1;
                rs1 += p2 + p3;
                s[nt][0] = to_tf32(p0); s[nt][1] = to_tf32(p1);
                s[nt][2] = to_tf32(p2); s[nt][3] = to_tf32(p3);
            }
            rs0 += __shfl_xor_sync(0xffffffffu, rs0, 1);
            rs0 += __shfl_xor_sync(0xffffffffu, rs0, 2);
            rs1 += __shfl_xor_sync(0xffffffffu, rs1, 1);
            rs1 += __shfl_xor_sync(0xffffffffu, rs1, 2);
            l0 = l0 * alpha0 + rs0;
            l1 = l1 * alpha1 + rs1;
#pragma unroll
            for (int nt = 0; nt < 8; ++nt) {
                o[nt][0] *= alpha0; o[nt][1] *= alpha0;
                o[nt][2] *= alpha1; o[nt][3] *= alpha1;
            }
        }

        // ---- phase C: O += P @ V (fragment permute via shfl, then mma) ----
        {
            const float* vb = sV[cur];
#pragma unroll
            for (int ks = 0; ks < 8; ++ks) {
                float lo0 = __shfl_sync(0xffffffffu, s[ks][0], srcA);
                float hi0 = __shfl_sync(0xffffffffu, s[ks][1], srcA);
                float a0 = oddq ? hi0 : lo0;
                float lo1 = __shfl_sync(0xffffffffu, s[ks][2], srcA);
                float hi1 = __shfl_sync(0xffffffffu, s[ks][3], srcA);
                float a1 = oddq ? hi1 : lo1;
                float lo2 = __shfl_sync(0xffffffffu, s[ks][0], srcB);
                float hi2 = __shfl_sync(0xffffffffu, s[ks][1], srcB);
                float a2 = oddq ? hi2 : lo2;
                float lo3 = __shfl_sync(0xffffffffu, s[ks][2], srcB);
                float hi3 = __shfl_sync(0xffffffffu, s[ks][3], srcB);
                float a3 = oddq ? hi3 : lo3;
#pragma unroll
                for (int nt = 0; nt < 8; ++nt) {
                    float b0 = vb[(8 * ks + q4) * VPAD + 8 * nt + g4];
                    float b1 = vb[(8 * ks + q4 + 4) * VPAD + 8 * nt + g4];
                    mma_tf32(o[nt], a0, a1, a2, a3, b0, b1);
                }
            }
        }

        if (pref) {
            *(float4*)&sKh[nxt][jj * KPAD + hh * 4] = khr;
            *(float4*)&sKl[nxt][jj * KPAD + hh * 4] = klr;
        }
        cp_wait0();
        __syncthreads();
    }

    // ---- epilogue: partials (fragment layout) + m/l ----
    const size_t sb = (size_t)(sp * 2 + b);
#pragma unroll
    for (int nt = 0; nt < 8; ++nt) {
        float2* d0 = (float2*)(g_Opart + (sb * N_SPAT + r0) * DV + 8 * nt + 2 * q4);
        *d0 = make_float2(o[nt][0], o[nt][1]);
        float2* d1 = (float2*)(g_Opart + (sb * N_SPAT + r1) * DV + 8 * nt + 2 * q4);
        *d1 = make_float2(o[nt][2], o[nt][3]);
    }
    if (q4 == 0) {
        g_m[sb * N_SPAT + r0] = m0;
        g_m[sb * N_SPAT + r1] = m1;
        g_l[sb * N_SPAT + r0] = l0;
        g_l[sb * N_SPAT + r1] = l1;
    }
}

// =====================================================================
// Merge kernel: combine JSPLIT partials (log-sum-exp, base-2 domain),
// transpose via smem, coalesced out[b][c][i] writes.
// =====================================================================
__global__ __launch_bounds__(256) void merge_kernel(float* __restrict__ out)
{
    __shared__ float T[DV][65];   // [c][i_local]

    const int b = blockIdx.y;
    const int i0 = blockIdx.x * 64;
    const int tid = threadIdx.x;
    const int il = tid >> 2;          // 0..63
    const int cq = tid & 3;           // channel quad group
    const int i = i0 + il;

    float mm[JSPLIT], coef[JSPLIT];
    float mstar = -CUDART_INF_F;
#pragma unroll
    for (int s = 0; s < JSPLIT; ++s) {
        mm[s] = g_m[((size_t)(s * 2 + b)) * N_SPAT + i];
        mstar = fmaxf(mstar, mm[s]);
    }
    float denom = 0.f;
#pragma unroll
    for (int s = 0; s < JSPLIT; ++s) {
        coef[s] = exp2f(mm[s] - mstar);
        denom += coef[s] * g_l[((size_t)(s * 2 + b)) * N_SPAT + i];
    }
    const float inv = 1.0f / denom;

    float acc[16];
#pragma unroll
    for (int e = 0; e < 16; ++e) acc[e] = 0.f;
#pragma unroll
    for (int s = 0; s < JSPLIT; ++s) {
        const float4* src = (const float4*)(g_Opart +
            (((size_t)(s * 2 + b)) * N_SPAT + i) * DV + cq * 16);
        float c = coef[s];
#pragma unroll
        for (int q = 0; q < 4; ++q) {
            float4 f = src[q];
            acc[4 * q + 0] = fmaf(c, f.x, acc[4 * q + 0]);
            acc[4 * q + 1] = fmaf(c, f.y, acc[4 * q + 1]);
            acc[4 * q + 2] = fmaf(c, f.z, acc[4 * q + 2]);
            acc[4 * q + 3] = fmaf(c, f.w, acc[4 * q + 3]);
        }
    }
#pragma unroll
    for (int e = 0; e < 16; ++e) T[cq * 16 + e][il] = acc[e] * inv;
    __syncthreads();

    {
        const int c = tid >> 2;
        const int ich = (tid & 3) * 16;
        float* dst = out + ((size_t)b * DV + c) * N_SPAT + i0 + ich;
#pragma unroll
        for (int q = 0; q < 4; ++q)
            ((float4*)dst)[q] = make_float4(T[c][ich + 4 * q + 0], T[c][ich + 4 * q + 1],
                                            T[c][ich + 4 * q + 2], T[c][ich + 4 * q + 3]);
    }
}

// =====================================================================
extern "C" void kernel_launch(void* const* d_in, const int* in_sizes, int n_in,
                              void* d_out, int out_size)
{
    const float* x  = (const float*)d_in[0];
    const float* wq = (const float*)d_in[1];
    const float* bq = (const float*)d_in[2];
    const float* wk = (const float*)d_in[3];
    const float* bk = (const float*)d_in[4];
    const float* wv = (const float*)d_in[5];
    const float* bv = (const float*)d_in[6];
    float* out = (float*)d_out;

    dim3 cgrid(5, 40, 2);                 // ocGroup, z*2+yhalf, batch
    conv_qkv_kernel<<<cgrid, CONV_T>>>(x, wq, bq, wk, bk, wv, bv);

    int n_round = NV_ELEM + 2 * NQ_ELEM;
    round_all_kernel<<<(n_round + 255) / 256, 256>>>();

    dim3 agrid(N_SPAT / BM, 2, JSPLIT);   // 125 x 2 x 2 = 500 CTAs
    attn_kernel<<<agrid, ATT_T>>>();

    dim3 mgrid(N_SPAT / 64, 2);
    merge_kernel<<<mgrid, 256>>>(out);
}

// round 14
// speedup vs baseline: 1.3895x; 1.2123x over previous
#include <cuda_runtime.h>
#include <math_constants.h>

#define N_SPAT 8000
#define CIN 64
#define DQK 8
#define DV 64
#define LOG2E_F 1.4426950408889634f
#define JSPLIT 2

typedef unsigned long long ull;

// ---------------- scratch (no allocations allowed) ----------------
__device__ float g_Q[2 * N_SPAT * DQK];             // hi part (scaled+tf32)
__device__ float g_Qlo[2 * N_SPAT * DQK];           // lo residual (tf32)
__device__ float g_K[2 * N_SPAT * DQK];             // hi part (tf32)
__device__ float g_Klo[2 * N_SPAT * DQK];           // lo residual (tf32)
__device__ float g_V[2 * N_SPAT * DV];              // tf32-rounded
__device__ float g_Opart[JSPLIT * 2 * N_SPAT * DV]; // [s][b][i][c]
__device__ float g_m[JSPLIT * 2 * N_SPAT];
__device__ float g_l[JSPLIT * 2 * N_SPAT];

// ---------------- f32x2 helpers ----------------
__device__ __forceinline__ ull dup2(float x) {
    ull r;
    asm("mov.b64 %0, {%1, %1};" : "=l"(r) : "r"(__float_as_uint(x)));
    return r;
}
__device__ __forceinline__ ull pack2(float lo, float hi) {
    ull r;
    asm("mov.b64 %0, {%1, %2};" : "=l"(r) : "r"(__float_as_uint(lo)), "r"(__float_as_uint(hi)));
    return r;
}
__device__ __forceinline__ void fma2(ull& d, ull a, ull b) {
    asm("fma.rn.f32x2 %0, %1, %2, %0;" : "+l"(d) : "l"(a), "l"(b));
}
__device__ __forceinline__ float lo32(ull v) { return __uint_as_float((unsigned)v); }
__device__ __forceinline__ float hi32(ull v) { return __uint_as_float((unsigned)(v >> 32)); }

// ---------------- tf32 / mma helpers ----------------
__device__ __forceinline__ float to_tf32(float x) {
    unsigned r;
    asm("cvt.rna.tf32.f32 %0, %1;" : "=r"(r) : "f"(x));
    return __uint_as_float(r);
}
__device__ __forceinline__ void mma_tf32(float* c,
    float a0, float a1, float a2, float a3, float b0, float b1)
{
    asm volatile(
        "mma.sync.aligned.m16n8k8.row.col.f32.tf32.tf32.f32 "
        "{%0,%1,%2,%3},{%4,%5,%6,%7},{%8,%9},{%0,%1,%2,%3};"
        : "+f"(c[0]), "+f"(c[1]), "+f"(c[2]), "+f"(c[3])
        : "r"(__float_as_uint(a0)), "r"(__float_as_uint(a1)),
          "r"(__float_as_uint(a2)), "r"(__float_as_uint(a3)),
          "r"(__float_as_uint(b0)), "r"(__float_as_uint(b1)));
}
__device__ __forceinline__ void mma_tf32_z(float* d,
    float a0, float a1, float a2, float a3, float b0, float b1)
{
    asm volatile(
        "mma.sync.aligned.m16n8k8.row.col.f32.tf32.tf32.f32 "
        "{%0,%1,%2,%3},{%4,%5,%6,%7},{%8,%9},{%10,%10,%10,%10};"
        : "=f"(d[0]), "=f"(d[1]), "=f"(d[2]), "=f"(d[3])
        : "r"(__float_as_uint(a0)), "r"(__float_as_uint(a1)),
          "r"(__float_as_uint(a2)), "r"(__float_as_uint(a3)),
          "r"(__float_as_uint(b0)), "r"(__float_as_uint(b1)), "f"(0.f));
}

// ---------------- cp.async helpers ----------------
__device__ __forceinline__ void cp_async16(void* smem, const void* gmem) {
    unsigned saddr = (unsigned)__cvta_generic_to_shared(smem);
    asm volatile("cp.async.cg.shared.global [%0], [%1], 16;\n" :: "r"(saddr), "l"(gmem));
}
__device__ __forceinline__ void cp_commit() { asm volatile("cp.async.commit_group;\n"); }
__device__ __forceinline__ void cp_wait0() { asm volatile("cp.async.wait_group 0;\n"); }

// =====================================================================
// Conv kernel: fused Q/K/V 3x3x3 SAME conv, mixed scalar/tensor.
// Grid (6 groups, 20 z, 2 b) = 240 CTAs, 256 threads, 68KB dyn smem.
//   g=0: Q (8 oc) scalar exact FFMA2    g=1: K (8 oc) scalar exact
//   g=2..5: V (16 oc each) via mma.m16n8k8.tf32 implicit GEMM
// Slab: full padded z-plane [8 ic][3 dz][22x22], ic stride 1480 words
// (1480 mod 32 == 8 -> b-fragment LDS conflict-free).
// Weights wsm[tap 27][ic 8][24 pad]: oc pairs contiguous (scalar LDS.128),
// mma A frags at stride 24 (conflict-free).
// =====================================================================
#define CONV_T 256
#define SLAB_IC 1480                       // words per ic (3*484=1452 used)
#define WSM_OFF (8 * SLAB_IC)              // 11840 words
#define CONV_SMEM ((8 * SLAB_IC + 27 * 8 * 24) * 4)   // 68096 B

__global__ __launch_bounds__(CONV_T) void conv_qkv_kernel(
    const float* __restrict__ x,
    const float* __restrict__ wq, const float* __restrict__ bq,
    const float* __restrict__ wk, const float* __restrict__ bk,
    const float* __restrict__ wv, const float* __restrict__ bv)
{
    extern __shared__ __align__(16) float csm[];
    float* slab = csm;                // [ic]*1480 + dz*484 + (y+dy)*22 + (x+dx)
    float* wsm  = csm + WSM_OFF;      // [tap]*192 + ic*24 + ocl

    const int g = blockIdx.x;
    const int z = blockIdx.y;
    const int b = blockIdx.z;
    const int tid = threadIdx.x;
    const bool tensor = (g >= 2);

    // ---- scalar state (g<2): 8 oc, 2 voxels (tid, tid+200) ----
    ull acc[2][4];
    const int y1 = (tid < 200) ? tid / 20 : 0;
    const int xc = (tid < 200) ? tid % 20 : 0;
    if (!tensor) {
        const float* bias = (g == 0) ? bq : bk;
#pragma unroll
        for (int p = 0; p < 4; ++p) {
            ull bb = pack2(bias[2 * p], bias[2 * p + 1]);
            acc[0][p] = bb; acc[1][p] = bb;
        }
    }

    // ---- tensor state (g>=2): mma over n-tiles ----
    const int w  = tid >> 5;
    const int lane = tid & 31;
    const int g4 = lane >> 2;
    const int q4 = lane & 3;
    const int ntc = (w < 2) ? 7 : 6;   // n-tiles: nt = w, w+8, ... (<50)
    float o[7][4];
    int voff[7];
    if (tensor) {
#pragma unroll
        for (int j = 0; j < 7; ++j) {
#pragma unroll
            for (int e = 0; e < 4; ++e) o[j][e] = 0.f;
            int nt = w + 8 * j;
            int v = 8 * nt + g4;
            if (nt < 50) voff[j] = (v / 20) * 22 + (v % 20);
            else voff[j] = 0;
        }
    }

    for (int chunk = 0; chunk < 8; ++chunk) {
        const int icbase = chunk * 8;
        __syncthreads();
        // ---- fill slab (zero borders); tensor CTAs round x to tf32 ----
        for (int idx = tid; idx < 8 * 1452; idx += CONV_T) {
            int ic = idx / 1452;
            int rem = idx % 1452;
            int zz = rem / 484;
            int spl = rem % 484;
            int yy = spl / 22 - 1;
            int xx = spl % 22 - 1;
            int zg = z + zz - 1;
            float v = 0.f;
            if ((unsigned)zg < 20u && (unsigned)yy < 20u && (unsigned)xx < 20u)
                v = x[(((size_t)b * 64 + icbase + ic) * 20 + zg) * 400 + yy * 20 + xx];
            if (tensor) v = to_tf32(v);
            slab[ic * SLAB_IC + rem] = v;
        }
        // ---- fill weights [tap][ic][ocl] ----
        for (int idx = tid; idx < 8 * 27 * 16; idx += CONV_T) {
            int ocl = idx & 15;
            int tap = (idx >> 4) % 27;
            int ic = idx / (27 * 16);
            int icg = icbase + ic;
            float wv_;
            if (g == 0)      wv_ = (ocl < 8) ? wq[((size_t)ocl * 64 + icg) * 27 + tap] : 0.f;
            else if (g == 1) wv_ = (ocl < 8) ? wk[((size_t)ocl * 64 + icg) * 27 + tap] : 0.f;
            else             wv_ = to_tf32(wv[((size_t)((g - 2) * 16 + ocl) * 64 + icg) * 27 + tap]);
            wsm[tap * 192 + ic * 24 + ocl] = wv_;
        }
        __syncthreads();

        if (!tensor) {
            if (tid < 200) {
#pragma unroll 2
                for (int ic = 0; ic < 8; ++ic) {
#pragma unroll
                    for (int dz = 0; dz < 3; ++dz) {
                        const float* sl1 = slab + ic * SLAB_IC + dz * 484 + y1 * 22 + xc;
                        const float* sl2 = sl1 + 220;   // +10 rows
#pragma unroll
                        for (int t9 = 0; t9 < 9; ++t9) {
                            const int off = (t9 / 3) * 22 + (t9 % 3);
                            ull xd1 = dup2(sl1[off]);
                            ull xd2 = dup2(sl2[off]);
                            const ulonglong2* wp =
                                (const ulonglong2*)(wsm + (dz * 9 + t9) * 192 + ic * 24);
                            ulonglong2 wA = wp[0], wB = wp[1];
                            fma2(acc[0][0], wA.x, xd1);
                            fma2(acc[0][1], wA.y, xd1);
                            fma2(acc[0][2], wB.x, xd1);
                            fma2(acc[0][3], wB.y, xd1);
                            fma2(acc[1][0], wA.x, xd2);
                            fma2(acc[1][1], wA.y, xd2);
                            fma2(acc[1][2], wB.x, xd2);
                            fma2(acc[1][3], wB.y, xd2);
                        }
                    }
                }
            }
        } else {
#pragma unroll
            for (int dz = 0; dz < 3; ++dz) {
#pragma unroll
                for (int dy = 0; dy < 3; ++dy) {
#pragma unroll
                    for (int dx = 0; dx < 3; ++dx) {
                        const int tap = dz * 9 + dy * 3 + dx;
                        const float* wt = wsm + tap * 192;
                        float a0 = wt[q4 * 24 + g4];
                        float a1 = wt[q4 * 24 + g4 + 8];
                        float a2 = wt[(q4 + 4) * 24 + g4];
                        float a3 = wt[(q4 + 4) * 24 + g4 + 8];
                        const float* bbase = slab + q4 * SLAB_IC + dz * 484 + dy * 22 + dx;
#pragma unroll
                        for (int j = 0; j < 7; ++j) {
                            if (j >= ntc) break;
                            const float* bp = bbase + voff[j];
                            mma_tf32(o[j], a0, a1, a2, a3, bp[0], bp[4 * SLAB_IC]);
                        }
                    }
                }
            }
        }
    }

    // ---- epilogues ----
    if (!tensor) {
        if (tid < 200) {
            float* dst = (g == 0) ? g_Q : g_K;
#pragma unroll
            for (int v = 0; v < 2; ++v) {
                int i = z * 400 + tid + v * 200;
                float4* d = (float4*)(dst + ((size_t)b * N_SPAT + i) * DQK);
                d[0] = make_float4(lo32(acc[v][0]), hi32(acc[v][0]),
                                   lo32(acc[v][1]), hi32(acc[v][1]));
                d[1] = make_float4(lo32(acc[v][2]), hi32(acc[v][2]),
                                   lo32(acc[v][3]), hi32(acc[v][3]));
            }
        }
    } else {
        const int oc0 = (g - 2) * 16 + g4;
        const float bias0 = bv[oc0];
        const float bias1 = bv[oc0 + 8];
#pragma unroll
        for (int j = 0; j < 7; ++j) {
            if (j >= ntc) break;
            int nt = w + 8 * j;
            int iv = z * 400 + 8 * nt + 2 * q4;
            float* d0 = g_V + ((size_t)b * N_SPAT + iv) * DV + oc0;
            float* d1 = g_V + ((size_t)b * N_SPAT + iv + 1) * DV + oc0;
            d0[0] = o[j][0] + bias0;
            d1[0] = o[j][1] + bias0;
            d0[8] = o[j][2] + bias1;
            d1[8] = o[j][3] + bias1;
        }
    }
}

// =====================================================================
// Round: V -> tf32; Q (scaled by log2e) and K -> hi/lo tf32 split.
// =====================================================================
#define NV_ELEM (2 * N_SPAT * DV)
#define NQ_ELEM (2 * N_SPAT * DQK)

__global__ __launch_bounds__(256) void round_all_kernel()
{
    int idx = blockIdx.x * 256 + threadIdx.x;
    if (idx < NV_ELEM) {
        g_V[idx] = to_tf32(g_V[idx]);
    } else if (idx < NV_ELEM + NQ_ELEM) {
        int j = idx - NV_ELEM;
        float qs = g_Q[j] * LOG2E_F;
        float hi = to_tf32(qs);
        g_Q[j] = hi;
        g_Qlo[j] = to_tf32(qs - hi);
    } else if (idx < NV_ELEM + 2 * NQ_ELEM) {
        int j = idx - NV_ELEM - NQ_ELEM;
        float k = g_K[j];
        float hi = to_tf32(k);
        g_K[j] = hi;
        g_Klo[j] = to_tf32(k - hi);
    }
}

// =====================================================================
// Flash attention (split-KV partials), ALL-mma with 3xTF32 exact QK.
// (R13, proven: 492us total / rel_err 2.15e-4.)
// =====================================================================
#define BM 64
#define BN 64
#define ATT_T 128
#define KPAD 12
#define VPAD 72

__global__ __launch_bounds__(ATT_T, 4) void attn_kernel()
{
    __shared__ __align__(16) float sKh[2][BN * KPAD];
    __shared__ __align__(16) float sKl[2][BN * KPAD];
    __shared__ __align__(16) float sV[2][BN * VPAD];

    const int b = blockIdx.y;
    const int sp = blockIdx.z;
    const int i0 = blockIdx.x * BM;
    const int tid = threadIdx.x;
    const int w = tid >> 5;
    const int lane = tid & 31;
    const int g4 = lane >> 2;
    const int q4 = lane & 3;

    const int NT = N_SPAT / BN;       // 125
    const int t0 = (sp * NT) / JSPLIT;
    const int t1 = ((sp + 1) * NT) / JSPLIT;

    const float* Qb  = g_Q   + (size_t)b * N_SPAT * DQK;
    const float* Qlb = g_Qlo + (size_t)b * N_SPAT * DQK;
    const float* Kb  = g_K   + (size_t)b * N_SPAT * DQK;
    const float* Klb = g_Klo + (size_t)b * N_SPAT * DQK;
    const float* Vb  = g_V   + (size_t)b * N_SPAT * DV;

    const int r0 = i0 + 16 * w + g4;
    const int r1 = r0 + 8;
    const float ah0 = Qb[r0 * DQK + q4];
    const float ah1 = Qb[r1 * DQK + q4];
    const float ah2 = Qb[r0 * DQK + q4 + 4];
    const float ah3 = Qb[r1 * DQK + q4 + 4];
    const float al0 = Qlb[r0 * DQK + q4];
    const float al1 = Qlb[r1 * DQK + q4];
    const float al2 = Qlb[r0 * DQK + q4 + 4];
    const float al3 = Qlb[r1 * DQK + q4 + 4];

    float m0 = -CUDART_INF_F, m1 = -CUDART_INF_F, l0 = 0.f, l1 = 0.f;
    float o[8][4];
#pragma unroll
    for (int nt = 0; nt < 8; ++nt)
#pragma unroll
        for (int e = 0; e < 4; ++e) o[nt][e] = 0.f;

    const int jj = tid >> 1, hh = tid & 1;

    {
        float4 kh = ((const float4*)(Kb + (size_t)t0 * BN * DQK))[tid];
        float4 kl = ((const float4*)(Klb + (size_t)t0 * BN * DQK))[tid];
        const float* vsrc = Vb + (size_t)t0 * BN * DV;
#pragma unroll
        for (int q = 0; q < 8; ++q) {
            int ch = tid + q * 128;
            int row = ch >> 4, off = ch & 15;
            cp_async16(&sV[0][row * VPAD + off * 4], vsrc + row * 64 + off * 4);
        }
        cp_commit();
        *(float4*)&sKh[0][jj * KPAD + hh * 4] = kh;
        *(float4*)&sKl[0][jj * KPAD + hh * 4] = kl;
        cp_wait0();
        __syncthreads();
    }

    const int srcA = (g4 << 2) + (q4 >> 1);
    const int srcB = srcA + 2;
    const bool oddq = (q4 & 1);

    for (int it = t0; it < t1; ++it) {
        const int cur = (it - t0) & 1;
        const int nxt = cur ^ 1;
        const bool pref = (it + 1 < t1);
        float4 khr, klr;
        if (pref) {
            khr = ((const float4*)(Kb + (size_t)(it + 1) * BN * DQK))[tid];
            klr = ((const float4*)(Klb + (size_t)(it + 1) * BN * DQK))[tid];
            const float* vsrc = Vb + (size_t)(it + 1) * BN * DV;
#pragma unroll
            for (int q = 0; q < 8; ++q) {
                int ch = tid + q * 128;
                int row = ch >> 4, off = ch & 15;
                cp_async16(&sV[nxt][row * VPAD + off * 4], vsrc + row * 64 + off * 4);
            }
            cp_commit();
        }

        float s[8][4];
        {
            const float* kbh = sKh[cur];
            const float* kbl = sKl[cur];
#pragma unroll
            for (int nt = 0; nt < 8; ++nt) {
                float b0h = kbh[(8 * nt + g4) * KPAD + q4];
                float b1h = kbh[(8 * nt + g4) * KPAD + q4 + 4];
                float b0l = kbl[(8 * nt + g4) * KPAD + q4];
                float b1l = kbl[(8 * nt + g4) * KPAD + q4 + 4];
                mma_tf32_z(s[nt], ah0, ah1, ah2, ah3, b0h, b1h);
                mma_tf32 (s[nt], ah0, ah1, ah2, ah3, b0l, b1l);
                mma_tf32 (s[nt], al0, al1, al2, al3, b0h, b1h);
            }
        }

        {
            float mx0 = fmaxf(s[0][0], s[0][1]);
            float mx1 = fmaxf(s[0][2], s[0][3]);
#pragma unroll
            for (int nt = 1; nt < 8; ++nt) {
                mx0 = fmaxf(mx0, fmaxf(s[nt][0], s[nt][1]));
                mx1 = fmaxf(mx1, fmaxf(s[nt][2], s[nt][3]));
            }
            mx0 = fmaxf(mx0, __shfl_xor_sync(0xffffffffu, mx0, 1));
            mx0 = fmaxf(mx0, __shfl_xor_sync(0xffffffffu, mx0, 2));
            mx1 = fmaxf(mx1, __shfl_xor_sync(0xffffffffu, mx1, 1));
            mx1 = fmaxf(mx1, __shfl_xor_sync(0xffffffffu, mx1, 2));
            float m0n = fmaxf(m0, mx0);
            float m1n = fmaxf(m1, mx1);
            float alpha0 = exp2f(m0 - m0n);
            float alpha1 = exp2f(m1 - m1n);
            m0 = m0n; m1 = m1n;
            float rs0 = 0.f, rs1 = 0.f;
#pragma unroll
            for (int nt = 0; nt < 8; ++nt) {
                float p0 = exp2f(s[nt][0] - m0);
                float p1 = exp2f(s[nt][1] - m0);
                float p2 = exp2f(s[nt][2] - m1);
                float p3 = exp2f(s[nt][3] - m1);
                rs0 += p0 + p1;
                rs1 += p2 + p3;
                s[nt][0] = to_tf32(p0); s[nt][1] = to_tf32(p1);
                s[nt][2] = to_tf32(p2); s[nt][3] = to_tf32(p3);
            }
            rs0 += __shfl_xor_sync(0xffffffffu, rs0, 1);
            rs0 += __shfl_xor_sync(0xffffffffu, rs0, 2);
            rs1 += __shfl_xor_sync(0xffffffffu, rs1, 1);
            rs1 += __shfl_xor_sync(0xffffffffu, rs1, 2);
            l0 = l0 * alpha0 + rs0;
            l1 = l1 * alpha1 + rs1;
#pragma unroll
            for (int nt = 0; nt < 8; ++nt) {
                o[nt][0] *= alpha0; o[nt][1] *= alpha0;
                o[nt][2] *= alpha1; o[nt][3] *= alpha1;
            }
        }

        {
            const float* vb = sV[cur];
#pragma unroll
            for (int ks = 0; ks < 8; ++ks) {
                float lo0 = __shfl_sync(0xffffffffu, s[ks][0], srcA);
                float hi0 = __shfl_sync(0xffffffffu, s[ks][1], srcA);
                float a0 = oddq ? hi0 : lo0;
                float lo1 = __shfl_sync(0xffffffffu, s[ks][2], srcA);
                float hi1 = __shfl_sync(0xffffffffu, s[ks][3], srcA);
                float a1 = oddq ? hi1 : lo1;
                float lo2 = __shfl_sync(0xffffffffu, s[ks][0], srcB);
                float hi2 = __shfl_sync(0xffffffffu, s[ks][1], srcB);
                float a2 = oddq ? hi2 : lo2;
                float lo3 = __shfl_sync(0xffffffffu, s[ks][2], srcB);
                float hi3 = __shfl_sync(0xffffffffu, s[ks][3], srcB);
                float a3 = oddq ? hi3 : lo3;
#pragma unroll
                for (int nt = 0; nt < 8; ++nt) {
                    float b0 = vb[(8 * ks + q4) * VPAD + 8 * nt + g4];
                    float b1 = vb[(8 * ks + q4 + 4) * VPAD + 8 * nt + g4];
                    mma_tf32(o[nt], a0, a1, a2, a3, b0, b1);
                }
            }
        }

        if (pref) {
            *(float4*)&sKh[nxt][jj * KPAD + hh * 4] = khr;
            *(float4*)&sKl[nxt][jj * KPAD + hh * 4] = klr;
        }
        cp_wait0();
        __syncthreads();
    }

    const size_t sb = (size_t)(sp * 2 + b);
#pragma unroll
    for (int nt = 0; nt < 8; ++nt) {
        float2* d0 = (float2*)(g_Opart + (sb * N_SPAT + r0) * DV + 8 * nt + 2 * q4);
        *d0 = make_float2(o[nt][0], o[nt][1]);
        float2* d1 = (float2*)(g_Opart + (sb * N_SPAT + r1) * DV + 8 * nt + 2 * q4);
        *d1 = make_float2(o[nt][2], o[nt][3]);
    }
    if (q4 == 0) {
        g_m[sb * N_SPAT + r0] = m0;
        g_m[sb * N_SPAT + r1] = m1;
        g_l[sb * N_SPAT + r0] = l0;
        g_l[sb * N_SPAT + r1] = l1;
    }
}

// =====================================================================
// Merge kernel: combine JSPLIT partials (log-sum-exp, base-2 domain).
// =====================================================================
__global__ __launch_bounds__(256) void merge_kernel(float* __restrict__ out)
{
    __shared__ float T[DV][65];

    const int b = blockIdx.y;
    const int i0 = blockIdx.x * 64;
    const int tid = threadIdx.x;
    const int il = tid >> 2;
    const int cq = tid & 3;
    const int i = i0 + il;

    float mm[JSPLIT], coef[JSPLIT];
    float mstar = -CUDART_INF_F;
#pragma unroll
    for (int s = 0; s < JSPLIT; ++s) {
        mm[s] = g_m[((size_t)(s * 2 + b)) * N_SPAT + i];
        mstar = fmaxf(mstar, mm[s]);
    }
    float denom = 0.f;
#pragma unroll
    for (int s = 0; s < JSPLIT; ++s) {
        coef[s] = exp2f(mm[s] - mstar);
        denom += coef[s] * g_l[((size_t)(s * 2 + b)) * N_SPAT + i];
    }
    const float inv = 1.0f / denom;

    float acc[16];
#pragma unroll
    for (int e = 0; e < 16; ++e) acc[e] = 0.f;
#pragma unroll
    for (int s = 0; s < JSPLIT; ++s) {
        const float4* src = (const float4*)(g_Opart +
            (((size_t)(s * 2 + b)) * N_SPAT + i) * DV + cq * 16);
        float c = coef[s];
#pragma unroll
        for (int q = 0; q < 4; ++q) {
            float4 f = src[q];
            acc[4 * q + 0] = fmaf(c, f.x, acc[4 * q + 0]);
            acc[4 * q + 1] = fmaf(c, f.y, acc[4 * q + 1]);
            acc[4 * q + 2] = fmaf(c, f.z, acc[4 * q + 2]);
            acc[4 * q + 3] = fmaf(c, f.w, acc[4 * q + 3]);
        }
    }
#pragma unroll
    for (int e = 0; e < 16; ++e) T[cq * 16 + e][il] = acc[e] * inv;
    __syncthreads();

    {
        const int c = tid >> 2;
        const int ich = (tid & 3) * 16;
        float* dst = out + ((size_t)b * DV + c) * N_SPAT + i0 + ich;
#pragma unroll
        for (int q = 0; q < 4; ++q)
            ((float4*)dst)[q] = make_float4(T[c][ich + 4 * q + 0], T[c][ich + 4 * q + 1],
                                            T[c][ich + 4 * q + 2], T[c][ich + 4 * q + 3]);
    }
}

// =====================================================================
extern "C" void kernel_launch(void* const* d_in, const int* in_sizes, int n_in,
                              void* d_out, int out_size)
{
    const float* x  = (const float*)d_in[0];
    const float* wq = (const float*)d_in[1];
    const float* bq = (const float*)d_in[2];
    const float* wk = (const float*)d_in[3];
    const float* bk = (const float*)d_in[4];
    const float* wv = (const float*)d_in[5];
    const float* bv = (const float*)d_in[6];
    float* out = (float*)d_out;

    cudaFuncSetAttribute(conv_qkv_kernel,
                         cudaFuncAttributeMaxDynamicSharedMemorySize,
                         CONV_SMEM);

    dim3 cgrid(6, 20, 2);                 // group, z, batch = 240 CTAs
    conv_qkv_kernel<<<cgrid, CONV_T, CONV_SMEM>>>(x, wq, bq, wk, bk, wv, bv);

    int n_round = NV_ELEM + 2 * NQ_ELEM;
    round_all_kernel<<<(n_round + 255) / 256, 256>>>();

    dim3 agrid(N_SPAT / BM, 2, JSPLIT);   // 125 x 2 x 2 = 500 CTAs
    attn_kernel<<<agrid, ATT_T>>>();

    dim3 mgrid(N_SPAT / 64, 2);
    merge_kernel<<<mgrid, 256>>>(out);
}

// round 15
// speedup vs baseline: 1.3899x; 1.0002x over previous
#include <cuda_runtime.h>
#include <math_constants.h>

#define N_SPAT 8000
#define CIN 64
#define DQK 8
#define DV 64
#define LOG2E_F 1.4426950408889634f
#define JSPLIT 2

typedef unsigned long long ull;

// ---------------- scratch (no allocations allowed) ----------------
__device__ float g_Q[2 * N_SPAT * DQK];             // hi part (scaled+tf32)
__device__ float g_Qlo[2 * N_SPAT * DQK];           // lo residual (tf32)
__device__ float g_K[2 * N_SPAT * DQK];             // hi part (tf32)
__device__ float g_Klo[2 * N_SPAT * DQK];           // lo residual (tf32)
__device__ float g_V[2 * N_SPAT * DV];              // tf32-rounded
__device__ float g_Opart[JSPLIT * 2 * N_SPAT * DV]; // [s][b][i][c]
__device__ float g_m[JSPLIT * 2 * N_SPAT];
__device__ float g_l[JSPLIT * 2 * N_SPAT];

// ---------------- f32x2 helpers ----------------
__device__ __forceinline__ ull dup2(float x) {
    ull r;
    asm("mov.b64 %0, {%1, %1};" : "=l"(r) : "r"(__float_as_uint(x)));
    return r;
}
__device__ __forceinline__ ull pack2(float lo, float hi) {
    ull r;
    asm("mov.b64 %0, {%1, %2};" : "=l"(r) : "r"(__float_as_uint(lo)), "r"(__float_as_uint(hi)));
    return r;
}
__device__ __forceinline__ void fma2(ull& d, ull a, ull b) {
    asm("fma.rn.f32x2 %0, %1, %2, %0;" : "+l"(d) : "l"(a), "l"(b));
}
__device__ __forceinline__ float lo32(ull v) { return __uint_as_float((unsigned)v); }
__device__ __forceinline__ float hi32(ull v) { return __uint_as_float((unsigned)(v >> 32)); }

// ---------------- tf32 / mma helpers ----------------
__device__ __forceinline__ float to_tf32(float x) {
    unsigned r;
    asm("cvt.rna.tf32.f32 %0, %1;" : "=r"(r) : "f"(x));
    return __uint_as_float(r);
}
__device__ __forceinline__ void mma_tf32(float* c,
    float a0, float a1, float a2, float a3, float b0, float b1)
{
    asm volatile(
        "mma.sync.aligned.m16n8k8.row.col.f32.tf32.tf32.f32 "
        "{%0,%1,%2,%3},{%4,%5,%6,%7},{%8,%9},{%0,%1,%2,%3};"
        : "+f"(c[0]), "+f"(c[1]), "+f"(c[2]), "+f"(c[3])
        : "r"(__float_as_uint(a0)), "r"(__float_as_uint(a1)),
          "r"(__float_as_uint(a2)), "r"(__float_as_uint(a3)),
          "r"(__float_as_uint(b0)), "r"(__float_as_uint(b1)));
}
__device__ __forceinline__ void mma_tf32_z(float* d,
    float a0, float a1, float a2, float a3, float b0, float b1)
{
    asm volatile(
        "mma.sync.aligned.m16n8k8.row.col.f32.tf32.tf32.f32 "
        "{%0,%1,%2,%3},{%4,%5,%6,%7},{%8,%9},{%10,%10,%10,%10};"
        : "=f"(d[0]), "=f"(d[1]), "=f"(d[2]), "=f"(d[3])
        : "r"(__float_as_uint(a0)), "r"(__float_as_uint(a1)),
          "r"(__float_as_uint(a2)), "r"(__float_as_uint(a3)),
          "r"(__float_as_uint(b0)), "r"(__float_as_uint(b1)), "f"(0.f));
}

// ---------------- cp.async helpers ----------------
__device__ __forceinline__ void cp_async16(void* smem, const void* gmem) {
    unsigned saddr = (unsigned)__cvta_generic_to_shared(smem);
    asm volatile("cp.async.cg.shared.global [%0], [%1], 16;\n" :: "r"(saddr), "l"(gmem));
}
__device__ __forceinline__ void cp_commit() { asm volatile("cp.async.commit_group;\n"); }
__device__ __forceinline__ void cp_wait0() { asm volatile("cp.async.wait_group 0;\n"); }

// =====================================================================
// Conv kernel: fused Q/K/V 3x3x3 SAME conv, mixed scalar/tensor,
// ONE WAVE: grid (4 groups, 20 z, 2 b) = 160 CTAs, 256 threads.
//   g=0: Q (8 oc) scalar exact + fused log2e-scale + hi/lo tf32 split
//   g=1: K (8 oc) scalar exact + fused hi/lo tf32 split
//   g=2/3: V (32 oc each) via mma.m16n8k8.tf32, fused post-bias tf32
// Slab [8 ic][3 dz][484], ic stride 1480 (mod 32 == 8, b-frag clean).
// Weights wsm[tap 27][ic 8][40]: ocl 0..31 (+8 pad); A-frag stride 40
// conflict-free; scalar oc pairs contiguous (LDS.128).
// Dyn smem: (8*1480 + 27*8*40)*4 = 81920 B.
// =====================================================================
#define CONV_T 256
#define SLAB_IC 1480
#define WSM_OFF (8 * SLAB_IC)
#define WSTRIDE 40
#define CONV_SMEM ((8 * SLAB_IC + 27 * 8 * WSTRIDE) * 4)

__global__ __launch_bounds__(CONV_T) void conv_qkv_kernel(
    const float* __restrict__ x,
    const float* __restrict__ wq, const float* __restrict__ bq,
    const float* __restrict__ wk, const float* __restrict__ bk,
    const float* __restrict__ wv, const float* __restrict__ bv)
{
    extern __shared__ __align__(16) float csm[];
    float* slab = csm;
    float* wsm  = csm + WSM_OFF;      // [tap]*320 + ic*40 + ocl

    const int g = blockIdx.x;
    const int z = blockIdx.y;
    const int b = blockIdx.z;
    const int tid = threadIdx.x;
    const bool tensor = (g >= 2);

    // ---- scalar state (g<2): 8 oc, 2 voxels (tid, tid+200) ----
    ull acc[2][4];
    const int y1 = (tid < 200) ? tid / 20 : 0;
    const int xc = (tid < 200) ? tid % 20 : 0;
    if (!tensor) {
        const float* bias = (g == 0) ? bq : bk;
#pragma unroll
        for (int p = 0; p < 4; ++p) {
            ull bb = pack2(bias[2 * p], bias[2 * p + 1]);
            acc[0][p] = bb; acc[1][p] = bb;
        }
    }

    // ---- tensor state (g>=2): 2 m-tiles x up-to-7 n-tiles ----
    const int w  = tid >> 5;
    const int lane = tid & 31;
    const int g4 = lane >> 2;
    const int q4 = lane & 3;
    const int ntc = (w < 2) ? 7 : 6;
    float o[2][7][4];
    int voff[7];
    if (tensor) {
#pragma unroll
        for (int j = 0; j < 7; ++j) {
#pragma unroll
            for (int e = 0; e < 4; ++e) { o[0][j][e] = 0.f; o[1][j][e] = 0.f; }
            int nt = w + 8 * j;
            int v = 8 * nt + g4;
            voff[j] = (nt < 50) ? (v / 20) * 22 + (v % 20) : 0;
        }
    }

    for (int chunk = 0; chunk < 8; ++chunk) {
        const int icbase = chunk * 8;
        __syncthreads();
        // ---- fill slab (zero borders); tensor CTAs round x to tf32 ----
        for (int idx = tid; idx < 8 * 1452; idx += CONV_T) {
            int ic = idx / 1452;
            int rem = idx % 1452;
            int zz = rem / 484;
            int spl = rem % 484;
            int yy = spl / 22 - 1;
            int xx = spl % 22 - 1;
            int zg = z + zz - 1;
            float v = 0.f;
            if ((unsigned)zg < 20u && (unsigned)yy < 20u && (unsigned)xx < 20u)
                v = x[(((size_t)b * 64 + icbase + ic) * 20 + zg) * 400 + yy * 20 + xx];
            if (tensor) v = to_tf32(v);
            slab[ic * SLAB_IC + rem] = v;
        }
        // ---- fill weights [tap][ic][ocl 0..31] ----
        for (int idx = tid; idx < 8 * 27 * 32; idx += CONV_T) {
            int ocl = idx & 31;
            int tap = (idx >> 5) % 27;
            int ic = idx / (27 * 32);
            int icg = icbase + ic;
            float wv_;
            if (g == 0)      wv_ = (ocl < 8) ? wq[((size_t)ocl * 64 + icg) * 27 + tap] : 0.f;
            else if (g == 1) wv_ = (ocl < 8) ? wk[((size_t)ocl * 64 + icg) * 27 + tap] : 0.f;
            else             wv_ = to_tf32(wv[((size_t)((g - 2) * 32 + ocl) * 64 + icg) * 27 + tap]);
            wsm[tap * (8 * WSTRIDE) + ic * WSTRIDE + ocl] = wv_;
        }
        __syncthreads();

        if (!tensor) {
            if (tid < 200) {
#pragma unroll 2
                for (int ic = 0; ic < 8; ++ic) {
#pragma unroll
                    for (int dz = 0; dz < 3; ++dz) {
                        const float* sl1 = slab + ic * SLAB_IC + dz * 484 + y1 * 22 + xc;
                        const float* sl2 = sl1 + 220;
#pragma unroll
                        for (int t9 = 0; t9 < 9; ++t9) {
                            const int off = (t9 / 3) * 22 + (t9 % 3);
                            ull xd1 = dup2(sl1[off]);
                            ull xd2 = dup2(sl2[off]);
                            const ulonglong2* wp = (const ulonglong2*)
                                (wsm + (dz * 9 + t9) * (8 * WSTRIDE) + ic * WSTRIDE);
                            ulonglong2 wA = wp[0], wB = wp[1];
                            fma2(acc[0][0], wA.x, xd1);
                            fma2(acc[0][1], wA.y, xd1);
                            fma2(acc[0][2], wB.x, xd1);
                            fma2(acc[0][3], wB.y, xd1);
                            fma2(acc[1][0], wA.x, xd2);
                            fma2(acc[1][1], wA.y, xd2);
                            fma2(acc[1][2], wB.x, xd2);
                            fma2(acc[1][3], wB.y, xd2);
                        }
                    }
                }
            }
        } else {
#pragma unroll
            for (int dz = 0; dz < 3; ++dz) {
#pragma unroll
                for (int dy = 0; dy < 3; ++dy) {
#pragma unroll
                    for (int dx = 0; dx < 3; ++dx) {
                        const float* wt = wsm + (dz * 9 + dy * 3 + dx) * (8 * WSTRIDE);
                        float a00 = wt[q4 * WSTRIDE + g4];
                        float a01 = wt[q4 * WSTRIDE + g4 + 8];
                        float a02 = wt[(q4 + 4) * WSTRIDE + g4];
                        float a03 = wt[(q4 + 4) * WSTRIDE + g4 + 8];
                        float a10 = wt[q4 * WSTRIDE + 16 + g4];
                        float a11 = wt[q4 * WSTRIDE + 16 + g4 + 8];
                        float a12 = wt[(q4 + 4) * WSTRIDE + 16 + g4];
                        float a13 = wt[(q4 + 4) * WSTRIDE + 16 + g4 + 8];
                        const float* bbase = slab + q4 * SLAB_IC + dz * 484 + dy * 22 + dx;
#pragma unroll
                        for (int j = 0; j < 7; ++j) {
                            if (j >= ntc) break;
                            const float* bp = bbase + voff[j];
                            float b0 = bp[0];
                            float b1 = bp[4 * SLAB_IC];
                            mma_tf32(o[0][j], a00, a01, a02, a03, b0, b1);
                            mma_tf32(o[1][j], a10, a11, a12, a13, b0, b1);
                        }
                    }
                }
            }
        }
    }

    // ---- epilogues (rounding fused) ----
    if (!tensor) {
        if (tid < 200) {
            const bool isQ = (g == 0);
            float* dhi = isQ ? g_Q : g_K;
            float* dlo = isQ ? g_Qlo : g_Klo;
            const float scale = isQ ? LOG2E_F : 1.0f;
#pragma unroll
            for (int v = 0; v < 2; ++v) {
                int i = z * 400 + tid + v * 200;
                float vals[8];
#pragma unroll
                for (int p = 0; p < 4; ++p) {
                    vals[2 * p] = lo32(acc[v][p]);
                    vals[2 * p + 1] = hi32(acc[v][p]);
                }
                float hi[8], lo[8];
#pragma unroll
                for (int e = 0; e < 8; ++e) {
                    float s = vals[e] * scale;
                    hi[e] = to_tf32(s);
                    lo[e] = to_tf32(s - hi[e]);
                }
                float4* dh = (float4*)(dhi + ((size_t)b * N_SPAT + i) * DQK);
                dh[0] = make_float4(hi[0], hi[1], hi[2], hi[3]);
                dh[1] = make_float4(hi[4], hi[5], hi[6], hi[7]);
                float4* dl = (float4*)(dlo + ((size_t)b * N_SPAT + i) * DQK);
                dl[0] = make_float4(lo[0], lo[1], lo[2], lo[3]);
                dl[1] = make_float4(lo[4], lo[5], lo[6], lo[7]);
            }
        }
    } else {
#pragma unroll
        for (int mt = 0; mt < 2; ++mt) {
            const int oc0 = (g - 2) * 32 + mt * 16 + g4;
            const float bias0 = bv[oc0];
            const float bias1 = bv[oc0 + 8];
#pragma unroll
            for (int j = 0; j < 7; ++j) {
                if (j >= ntc) break;
                int nt = w + 8 * j;
                int iv = z * 400 + 8 * nt + 2 * q4;
                float* d0 = g_V + ((size_t)b * N_SPAT + iv) * DV + oc0;
                float* d1 = g_V + ((size_t)b * N_SPAT + iv + 1) * DV + oc0;
                d0[0] = to_tf32(o[mt][j][0] + bias0);
                d1[0] = to_tf32(o[mt][j][1] + bias0);
                d0[8] = to_tf32(o[mt][j][2] + bias1);
                d1[8] = to_tf32(o[mt][j][3] + bias1);
            }
        }
    }
}

// =====================================================================
// Flash attention (split-KV partials), ALL-mma with 3xTF32 exact QK.
// (R13, proven.)
// =====================================================================
#define BM 64
#define BN 64
#define ATT_T 128
#define KPAD 12
#define VPAD 72

__global__ __launch_bounds__(ATT_T, 4) void attn_kernel()
{
    __shared__ __align__(16) float sKh[2][BN * KPAD];
    __shared__ __align__(16) float sKl[2][BN * KPAD];
    __shared__ __align__(16) float sV[2][BN * VPAD];

    const int b = blockIdx.y;
    const int sp = blockIdx.z;
    const int i0 = blockIdx.x * BM;
    const int tid = threadIdx.x;
    const int w = tid >> 5;
    const int lane = tid & 31;
    const int g4 = lane >> 2;
    const int q4 = lane & 3;

    const int NT = N_SPAT / BN;       // 125
    const int t0 = (sp * NT) / JSPLIT;
    const int t1 = ((sp + 1) * NT) / JSPLIT;

    const float* Qb  = g_Q   + (size_t)b * N_SPAT * DQK;
    const float* Qlb = g_Qlo + (size_t)b * N_SPAT * DQK;
    const float* Kb  = g_K   + (size_t)b * N_SPAT * DQK;
    const float* Klb = g_Klo + (size_t)b * N_SPAT * DQK;
    const float* Vb  = g_V   + (size_t)b * N_SPAT * DV;

    const int r0 = i0 + 16 * w + g4;
    const int r1 = r0 + 8;
    const float ah0 = Qb[r0 * DQK + q4];
    const float ah1 = Qb[r1 * DQK + q4];
    const float ah2 = Qb[r0 * DQK + q4 + 4];
    const float ah3 = Qb[r1 * DQK + q4 + 4];
    const float al0 = Qlb[r0 * DQK + q4];
    const float al1 = Qlb[r1 * DQK + q4];
    const float al2 = Qlb[r0 * DQK + q4 + 4];
    const float al3 = Qlb[r1 * DQK + q4 + 4];

    float m0 = -CUDART_INF_F, m1 = -CUDART_INF_F, l0 = 0.f, l1 = 0.f;
    float o[8][4];
#pragma unroll
    for (int nt = 0; nt < 8; ++nt)
#pragma unroll
        for (int e = 0; e < 4; ++e) o[nt][e] = 0.f;

    const int jj = tid >> 1, hh = tid & 1;

    {
        float4 kh = ((const float4*)(Kb + (size_t)t0 * BN * DQK))[tid];
        float4 kl = ((const float4*)(Klb + (size_t)t0 * BN * DQK))[tid];
        const float* vsrc = Vb + (size_t)t0 * BN * DV;
#pragma unroll
        for (int q = 0; q < 8; ++q) {
            int ch = tid + q * 128;
            int row = ch >> 4, off = ch & 15;
            cp_async16(&sV[0][row * VPAD + off * 4], vsrc + row * 64 + off * 4);
        }
        cp_commit();
        *(float4*)&sKh[0][jj * KPAD + hh * 4] = kh;
        *(float4*)&sKl[0][jj * KPAD + hh * 4] = kl;
        cp_wait0();
        __syncthreads();
    }

    const int srcA = (g4 << 2) + (q4 >> 1);
    const int srcB = srcA + 2;
    const bool oddq = (q4 & 1);

    for (int it = t0; it < t1; ++it) {
        const int cur = (it - t0) & 1;
        const int nxt = cur ^ 1;
        const bool pref = (it + 1 < t1);
        float4 khr, klr;
        if (pref) {
            khr = ((const float4*)(Kb + (size_t)(it + 1) * BN * DQK))[tid];
            klr = ((const float4*)(Klb + (size_t)(it + 1) * BN * DQK))[tid];
            const float* vsrc = Vb + (size_t)(it + 1) * BN * DV;
#pragma unroll
            for (int q = 0; q < 8; ++q) {
                int ch = tid + q * 128;
                int row = ch >> 4, off = ch & 15;
                cp_async16(&sV[nxt][row * VPAD + off * 4], vsrc + row * 64 + off * 4);
            }
            cp_commit();
        }

        float s[8][4];
        {
            const float* kbh = sKh[cur];
            const float* kbl = sKl[cur];
#pragma unroll
            for (int nt = 0; nt < 8; ++nt) {
                float b0h = kbh[(8 * nt + g4) * KPAD + q4];
                float b1h = kbh[(8 * nt + g4) * KPAD + q4 + 4];
                float b0l = kbl[(8 * nt + g4) * KPAD + q4];
                float b1l = kbl[(8 * nt + g4) * KPAD + q4 + 4];
                mma_tf32_z(s[nt], ah0, ah1, ah2, ah3, b0h, b1h);
                mma_tf32 (s[nt], ah0, ah1, ah2, ah3, b0l, b1l);
                mma_tf32 (s[nt], al0, al1, al2, al3, b0h, b1h);
            }
        }

        {
            float mx0 = fmaxf(s[0][0], s[0][1]);
            float mx1 = fmaxf(s[0][2], s[0][3]);
#pragma unroll
            for (int nt = 1; nt < 8; ++nt) {
                mx0 = fmaxf(mx0, fmaxf(s[nt][0], s[nt][1]));
                mx1 = fmaxf(mx1, fmaxf(s[nt][2], s[nt][3]));
            }
            mx0 = fmaxf(mx0, __shfl_xor_sync(0xffffffffu, mx0, 1));
            mx0 = fmaxf(mx0, __shfl_xor_sync(0xffffffffu, mx0, 2));
            mx1 = fmaxf(mx1, __shfl_xor_sync(0xffffffffu, mx1, 1));
            mx1 = fmaxf(mx1, __shfl_xor_sync(0xffffffffu, mx1, 2));
            float m0n = fmaxf(m0, mx0);
            float m1n = fmaxf(m1, mx1);
            float alpha0 = exp2f(m0 - m0n);
            float alpha1 = exp2f(m1 - m1n);
            m0 = m0n; m1 = m1n;
            float rs0 = 0.f, rs1 = 0.f;
#pragma unroll
            for (int nt = 0; nt < 8; ++nt) {
                float p0 = exp2f(s[nt][0] - m0);
                float p1 = exp2f(s[nt][1] - m0);
                float p2 = exp2f(s[nt][2] - m1);
                float p3 = exp2f(s[nt][3] - m1);
                rs0 += p0 + p1;
                rs1 += p2 + p3;
                s[nt][0] = to_tf32(p0); s[nt][1] = to_tf32(p1);
                s[nt][2] = to_tf32(p2); s[nt][3] = to_tf32(p3);
            }
            rs0 += __shfl_xor_sync(0xffffffffu, rs0, 1);
            rs0 += __shfl_xor_sync(0xffffffffu, rs0, 2);
            rs1 += __shfl_xor_sync(0xffffffffu, rs1, 1);
            rs1 += __shfl_xor_sync(0xffffffffu, rs1, 2);
            l0 = l0 * alpha0 + rs0;
            l1 = l1 * alpha1 + rs1;
#pragma unroll
            for (int nt = 0; nt < 8; ++nt) {
                o[nt][0] *= alpha0; o[nt][1] *= alpha0;
                o[nt][2] *= alpha1; o[nt][3] *= alpha1;
            }
        }

        {
            const float* vb = sV[cur];
#pragma unroll
            for (int ks = 0; ks < 8; ++ks) {
                float lo0 = __shfl_sync(0xffffffffu, s[ks][0], srcA);
                float hi0 = __shfl_sync(0xffffffffu, s[ks][1], srcA);
                float a0 = oddq ? hi0 : lo0;
                float lo1 = __shfl_sync(0xffffffffu, s[ks][2], srcA);
                float hi1 = __shfl_sync(0xffffffffu, s[ks][3], srcA);
                float a1 = oddq ? hi1 : lo1;
                float lo2 = __shfl_sync(0xffffffffu, s[ks][0], srcB);
                float hi2 = __shfl_sync(0xffffffffu, s[ks][1], srcB);
                float a2 = oddq ? hi2 : lo2;
                float lo3 = __shfl_sync(0xffffffffu, s[ks][2], srcB);
                float hi3 = __shfl_sync(0xffffffffu, s[ks][3], srcB);
                float a3 = oddq ? hi3 : lo3;
#pragma unroll
                for (int nt = 0; nt < 8; ++nt) {
                    float b0 = vb[(8 * ks + q4) * VPAD + 8 * nt + g4];
                    float b1 = vb[(8 * ks + q4 + 4) * VPAD + 8 * nt + g4];
                    mma_tf32(o[nt], a0, a1, a2, a3, b0, b1);
                }
            }
        }

        if (pref) {
            *(float4*)&sKh[nxt][jj * KPAD + hh * 4] = khr;
            *(float4*)&sKl[nxt][jj * KPAD + hh * 4] = klr;
        }
        cp_wait0();
        __syncthreads();
    }

    const size_t sb = (size_t)(sp * 2 + b);
#pragma unroll
    for (int nt = 0; nt < 8; ++nt) {
        float2* d0 = (float2*)(g_Opart + (sb * N_SPAT + r0) * DV + 8 * nt + 2 * q4);
        *d0 = make_float2(o[nt][0], o[nt][1]);
        float2* d1 = (float2*)(g_Opart + (sb * N_SPAT + r1) * DV + 8 * nt + 2 * q4);
        *d1 = make_float2(o[nt][2], o[nt][3]);
    }
    if (q4 == 0) {
        g_m[sb * N_SPAT + r0] = m0;
        g_m[sb * N_SPAT + r1] = m1;
        g_l[sb * N_SPAT + r0] = l0;
        g_l[sb * N_SPAT + r1] = l1;
    }
}

// =====================================================================
// Merge kernel: combine JSPLIT partials (log-sum-exp, base-2 domain).
// =====================================================================
__global__ __launch_bounds__(256) void merge_kernel(float* __restrict__ out)
{
    __shared__ float T[DV][65];

    const int b = blockIdx.y;
    const int i0 = blockIdx.x * 64;
    const int tid = threadIdx.x;
    const int il = tid >> 2;
    const int cq = tid & 3;
    const int i = i0 + il;

    float mm[JSPLIT], coef[JSPLIT];
    float mstar = -CUDART_INF_F;
#pragma unroll
    for (int s = 0; s < JSPLIT; ++s) {
        mm[s] = g_m[((size_t)(s * 2 + b)) * N_SPAT + i];
        mstar = fmaxf(mstar, mm[s]);
    }
    float denom = 0.f;
#pragma unroll
    for (int s = 0; s < JSPLIT; ++s) {
        coef[s] = exp2f(mm[s] - mstar);
        denom += coef[s] * g_l[((size_t)(s * 2 + b)) * N_SPAT + i];
    }
    const float inv = 1.0f / denom;

    float acc[16];
#pragma unroll
    for (int e = 0; e < 16; ++e) acc[e] = 0.f;
#pragma unroll
    for (int s = 0; s < JSPLIT; ++s) {
        const float4* src = (const float4*)(g_Opart +
            (((size_t)(s * 2 + b)) * N_SPAT + i) * DV + cq * 16);
        float c = coef[s];
#pragma unroll
        for (int q = 0; q < 4; ++q) {
            float4 f = src[q];
            acc[4 * q + 0] = fmaf(c, f.x, acc[4 * q + 0]);
            acc[4 * q + 1] = fmaf(c, f.y, acc[4 * q + 1]);
            acc[4 * q + 2] = fmaf(c, f.z, acc[4 * q + 2]);
            acc[4 * q + 3] = fmaf(c, f.w, acc[4 * q + 3]);
        }
    }
#pragma unroll
    for (int e = 0; e < 16; ++e) T[cq * 16 + e][il] = acc[e] * inv;
    __syncthreads();

    {
        const int c = tid >> 2;
        const int ich = (tid & 3) * 16;
        float* dst = out + ((size_t)b * DV + c) * N_SPAT + i0 + ich;
#pragma unroll
        for (int q = 0; q < 4; ++q)
            ((float4*)dst)[q] = make_float4(T[c][ich + 4 * q + 0], T[c][ich + 4 * q + 1],
                                            T[c][ich + 4 * q + 2], T[c][ich + 4 * q + 3]);
    }
}

// =====================================================================
extern "C" void kernel_launch(void* const* d_in, const int* in_sizes, int n_in,
                              void* d_out, int out_size)
{
    const float* x  = (const float*)d_in[0];
    const float* wq = (const float*)d_in[1];
    const float* bq = (const float*)d_in[2];
    const float* wk = (const float*)d_in[3];
    const float* bk = (const float*)d_in[4];
    const float* wv = (const float*)d_in[5];
    const float* bv = (const float*)d_in[6];
    float* out = (float*)d_out;

    cudaFuncSetAttribute(conv_qkv_kernel,
                         cudaFuncAttributeMaxDynamicSharedMemorySize,
                         CONV_SMEM);

    dim3 cgrid(4, 20, 2);                 // group, z, batch = 160 CTAs
    conv_qkv_kernel<<<cgrid, CONV_T, CONV_SMEM>>>(x, wq, bq, wk, bk, wv, bv);

    dim3 agrid(N_SPAT / BM, 2, JSPLIT);   // 125 x 2 x 2 = 500 CTAs
    attn_kernel<<<agrid, ATT_T>>>();

    dim3 mgrid(N_SPAT / 64, 2);
    merge_kernel<<<mgrid, 256>>>(out);
}

// round 16
// speedup vs baseline: 1.4784x; 1.0637x over previous
#include <cuda_runtime.h>
#include <math_constants.h>

#define N_SPAT 8000
#define CIN 64
#define DQK 8
#define DV 64
#define LOG2E_F 1.4426950408889634f
#define JSPLIT 2

typedef unsigned long long ull;

// ---------------- scratch (no allocations allowed) ----------------
__device__ float g_Q[2 * N_SPAT * DQK];             // hi part (scaled+tf32)
__device__ float g_Qlo[2 * N_SPAT * DQK];           // lo residual (tf32)
__device__ float g_K[2 * N_SPAT * DQK];             // hi part (tf32)
__device__ float g_Klo[2 * N_SPAT * DQK];           // lo residual (tf32)
__device__ float g_V[2 * N_SPAT * DV];              // tf32-rounded
__device__ float g_Opart[JSPLIT * 2 * N_SPAT * DV]; // [s][b][i][c]
__device__ float g_m[JSPLIT * 2 * N_SPAT];
__device__ float g_l[JSPLIT * 2 * N_SPAT];

// ---------------- f32x2 helpers ----------------
__device__ __forceinline__ ull dup2(float x) {
    ull r;
    asm("mov.b64 %0, {%1, %1};" : "=l"(r) : "r"(__float_as_uint(x)));
    return r;
}
__device__ __forceinline__ ull pack2(float lo, float hi) {
    ull r;
    asm("mov.b64 %0, {%1, %2};" : "=l"(r) : "r"(__float_as_uint(lo)), "r"(__float_as_uint(hi)));
    return r;
}
__device__ __forceinline__ void fma2(ull& d, ull a, ull b) {
    asm("fma.rn.f32x2 %0, %1, %2, %0;" : "+l"(d) : "l"(a), "l"(b));
}
__device__ __forceinline__ float lo32(ull v) { return __uint_as_float((unsigned)v); }
__device__ __forceinline__ float hi32(ull v) { return __uint_as_float((unsigned)(v >> 32)); }

// ---------------- tf32 / mma helpers ----------------
__device__ __forceinline__ float to_tf32(float x) {
    unsigned r;
    asm("cvt.rna.tf32.f32 %0, %1;" : "=r"(r) : "f"(x));
    return __uint_as_float(r);
}
__device__ __forceinline__ void mma_tf32(float* c,
    float a0, float a1, float a2, float a3, float b0, float b1)
{
    asm volatile(
        "mma.sync.aligned.m16n8k8.row.col.f32.tf32.tf32.f32 "
        "{%0,%1,%2,%3},{%4,%5,%6,%7},{%8,%9},{%0,%1,%2,%3};"
        : "+f"(c[0]), "+f"(c[1]), "+f"(c[2]), "+f"(c[3])
        : "r"(__float_as_uint(a0)), "r"(__float_as_uint(a1)),
          "r"(__float_as_uint(a2)), "r"(__float_as_uint(a3)),
          "r"(__float_as_uint(b0)), "r"(__float_as_uint(b1)));
}
__device__ __forceinline__ void mma_tf32_z(float* d,
    float a0, float a1, float a2, float a3, float b0, float b1)
{
    asm volatile(
        "mma.sync.aligned.m16n8k8.row.col.f32.tf32.tf32.f32 "
        "{%0,%1,%2,%3},{%4,%5,%6,%7},{%8,%9},{%10,%10,%10,%10};"
        : "=f"(d[0]), "=f"(d[1]), "=f"(d[2]), "=f"(d[3])
        : "r"(__float_as_uint(a0)), "r"(__float_as_uint(a1)),
          "r"(__float_as_uint(a2)), "r"(__float_as_uint(a3)),
          "r"(__float_as_uint(b0)), "r"(__float_as_uint(b1)), "f"(0.f));
}

// ---------------- cp.async helpers ----------------
__device__ __forceinline__ void cp_async16(void* smem, const void* gmem) {
    unsigned saddr = (unsigned)__cvta_generic_to_shared(smem);
    asm volatile("cp.async.cg.shared.global [%0], [%1], 16;\n" :: "r"(saddr), "l"(gmem));
}
__device__ __forceinline__ void cp_commit() { asm volatile("cp.async.commit_group;\n"); }
__device__ __forceinline__ void cp_wait0() { asm volatile("cp.async.wait_group 0;\n"); }

// =====================================================================
// Conv kernel: fused Q/K/V 3x3x3 SAME conv, mixed scalar/tensor.
// Grid (6 groups, 40 = z*2+yhalf, 2 b) = 480 CTAs, 256 thr, smem 46.6KB
// (static) -> 3 CTAs/SM co-resident.
//   g=0: Q (8 oc) scalar exact + fused log2e-scale + hi/lo tf32 split
//   g=1: K (8 oc) scalar exact + fused hi/lo tf32 split
//   g=2..5: V (16 oc each) via mma.m16n8k8.tf32, fused post-bias tf32
// Half-plane slab [8 ic][stride 808]: per ic = [3 zz][12 rows][22 cols]
// (stride 808 mod 32 == 8 -> b-frag conflicts bounded, proven pattern).
// Fills are div/mod-free: warp w owns ic w; lanes 0..21 own columns;
// zz/r compile-time. Weights wsm[tap 27][ic 8][24]: scalar LDS.128 pairs
// at offset 0..7; A-frags at stride 24 (banks distinct).
// =====================================================================
#define CONV_T 256
#define SLAB_IC 808
#define WS 24

__global__ __launch_bounds__(CONV_T, 3) void conv_qkv_kernel(
    const float* __restrict__ x,
    const float* __restrict__ wq, const float* __restrict__ bq,
    const float* __restrict__ wk, const float* __restrict__ bk,
    const float* __restrict__ wv, const float* __restrict__ bv)
{
    __shared__ __align__(16) float slab[8 * SLAB_IC];   // 25856 B
    __shared__ __align__(16) float wsm[27 * 8 * WS];    // 20736 B

    const int g = blockIdx.x;
    const int z = blockIdx.y >> 1;
    const int yh = blockIdx.y & 1;
    const int b = blockIdx.z;
    const int tid = threadIdx.x;
    const int w = tid >> 5;
    const int lane = tid & 31;
    const bool tensor = (g >= 2);

    // ---- scalar per-thread voxel (tid<200): 8 oc, 1 voxel ----
    const int yl = (tid < 200) ? tid / 20 : 0;
    const int xc = (tid < 200) ? tid % 20 : 0;
    ull acc[4];
    if (!tensor) {
        const float* bias = (g == 0) ? bq : bk;
#pragma unroll
        for (int p = 0; p < 4; ++p) acc[p] = pack2(bias[2 * p], bias[2 * p + 1]);
    }

    // ---- tensor frag state: 1 m-tile (16 oc) x up-to-4 n-tiles ----
    const int g4 = lane >> 2;
    const int q4 = lane & 3;
    const int ntc = (w == 0) ? 4 : 3;     // 25 n-tiles over 8 warps
    float o[4][4];
    int voff[4];
    if (tensor) {
#pragma unroll
        for (int j = 0; j < 4; ++j) {
#pragma unroll
            for (int e = 0; e < 4; ++e) o[j][e] = 0.f;
            int nt = w + 8 * j;
            int v = 8 * nt + g4;
            voff[j] = (nt < 25) ? (v / 20) * 22 + (v % 20) : 0;
        }
    }

    // fill lane mapping (columns)
    const bool fact = (lane < 22);
    const int fx = lane - 1;
    const bool fxok = ((unsigned)fx < 20u);
    const int wocl = lane & 15, wtp = lane >> 4;   // weight-fill mapping

    for (int chunk = 0; chunk < 8; ++chunk) {
        const int icg = chunk * 8 + w;            // this warp's input channel
        __syncthreads();
        // ---- slab fill: warp w fills ic-slot w (div/mod-free) ----
        {
            const float* xb = x + ((size_t)b * 64 + icg) * 8000;
            float* sl = slab + w * SLAB_IC + lane;
#pragma unroll
            for (int zz = 0; zz < 3; ++zz) {
                int zg = z + zz - 1;
                bool zok = ((unsigned)zg < 20u);
                const float* xz = xb + zg * 400 + fx;
#pragma unroll
                for (int r = 0; r < 12; ++r) {
                    int y = yh * 10 + r - 1;
                    bool ok = fact && fxok && zok && ((unsigned)y < 20u);
                    float v = ok ? xz[y * 20] : 0.f;
                    if (tensor) v = to_tf32(v);
                    if (fact) sl[zz * 264 + r * 22] = v;
                }
            }
        }
        // ---- weight fill: warp w fills ic-slot w ----
        {
#pragma unroll
            for (int t = 0; t < 14; ++t) {
                int tap = 2 * t + wtp;
                if (tap < 27) {
                    float wv_;
                    if (g == 0)
                        wv_ = (wocl < 8) ? wq[((size_t)wocl * 64 + icg) * 27 + tap] : 0.f;
                    else if (g == 1)
                        wv_ = (wocl < 8) ? wk[((size_t)wocl * 64 + icg) * 27 + tap] : 0.f;
                    else
                        wv_ = to_tf32(wv[((size_t)((g - 2) * 16 + wocl) * 64 + icg) * 27 + tap]);
                    wsm[tap * (8 * WS) + w * WS + wocl] = wv_;
                }
            }
        }
        __syncthreads();

        if (!tensor) {
            if (tid < 200) {
#pragma unroll 2
                for (int ic = 0; ic < 8; ++ic) {
#pragma unroll
                    for (int dz = 0; dz < 3; ++dz) {
                        const float* sl = slab + ic * SLAB_IC + dz * 264 + yl * 22 + xc;
#pragma unroll
                        for (int t9 = 0; t9 < 9; ++t9) {
                            const int off = (t9 / 3) * 22 + (t9 % 3);
                            ull xd = dup2(sl[off]);
                            const ulonglong2* wp = (const ulonglong2*)
                                (wsm + (dz * 9 + t9) * (8 * WS) + ic * WS);
                            ulonglong2 wA = wp[0], wB = wp[1];
                            fma2(acc[0], wA.x, xd);
                            fma2(acc[1], wA.y, xd);
                            fma2(acc[2], wB.x, xd);
                            fma2(acc[3], wB.y, xd);
                        }
                    }
                }
            }
        } else {
#pragma unroll
            for (int dz = 0; dz < 3; ++dz) {
#pragma unroll
                for (int dy = 0; dy < 3; ++dy) {
#pragma unroll
                    for (int dx = 0; dx < 3; ++dx) {
                        const float* wt = wsm + (dz * 9 + dy * 3 + dx) * (8 * WS);
                        float a0 = wt[q4 * WS + g4];
                        float a1 = wt[q4 * WS + g4 + 8];
                        float a2 = wt[(q4 + 4) * WS + g4];
                        float a3 = wt[(q4 + 4) * WS + g4 + 8];
                        const float* bbase = slab + q4 * SLAB_IC + dz * 264 + dy * 22 + dx;
#pragma unroll
                        for (int j = 0; j < 4; ++j) {
                            if (j >= ntc) break;
                            const float* bp = bbase + voff[j];
                            mma_tf32(o[j], a0, a1, a2, a3, bp[0], bp[4 * SLAB_IC]);
                        }
                    }
                }
            }
        }
    }

    // ---- epilogues (rounding fused) ----
    if (!tensor) {
        if (tid < 200) {
            const bool isQ = (g == 0);
            float* dhi = isQ ? g_Q : g_K;
            float* dlo = isQ ? g_Qlo : g_Klo;
            const float scale = isQ ? LOG2E_F : 1.0f;
            const int i = z * 400 + yh * 200 + tid;
            float hi[8], lo[8];
#pragma unroll
            for (int p = 0; p < 4; ++p) {
                float s0 = lo32(acc[p]) * scale;
                float s1 = hi32(acc[p]) * scale;
                hi[2 * p] = to_tf32(s0);     lo[2 * p] = to_tf32(s0 - hi[2 * p]);
                hi[2 * p + 1] = to_tf32(s1); lo[2 * p + 1] = to_tf32(s1 - hi[2 * p + 1]);
            }
            float4* dh = (float4*)(dhi + ((size_t)b * N_SPAT + i) * DQK);
            dh[0] = make_float4(hi[0], hi[1], hi[2], hi[3]);
            dh[1] = make_float4(hi[4], hi[5], hi[6], hi[7]);
            float4* dl = (float4*)(dlo + ((size_t)b * N_SPAT + i) * DQK);
            dl[0] = make_float4(lo[0], lo[1], lo[2], lo[3]);
            dl[1] = make_float4(lo[4], lo[5], lo[6], lo[7]);
        }
    } else {
        const int oc0 = (g - 2) * 16 + g4;
        const float bias0 = bv[oc0];
        const float bias1 = bv[oc0 + 8];
#pragma unroll
        for (int j = 0; j < 4; ++j) {
            if (j >= ntc) break;
            int nt = w + 8 * j;
            int iv = z * 400 + yh * 200 + 8 * nt + 2 * q4;
            float* d0 = g_V + ((size_t)b * N_SPAT + iv) * DV + oc0;
            float* d1 = g_V + ((size_t)b * N_SPAT + iv + 1) * DV + oc0;
            d0[0] = to_tf32(o[j][0] + bias0);
            d1[0] = to_tf32(o[j][1] + bias0);
            d0[8] = to_tf32(o[j][2] + bias1);
            d1[8] = to_tf32(o[j][3] + bias1);
        }
    }
}

// =====================================================================
// Flash attention (split-KV partials), ALL-mma with 3xTF32 exact QK.
// (R13-R15, proven.)
// =====================================================================
#define BM 64
#define BN 64
#define ATT_T 128
#define KPAD 12
#define VPAD 72

__global__ __launch_bounds__(ATT_T, 4) void attn_kernel()
{
    __shared__ __align__(16) float sKh[2][BN * KPAD];
    __shared__ __align__(16) float sKl[2][BN * KPAD];
    __shared__ __align__(16) float sV[2][BN * VPAD];

    const int b = blockIdx.y;
    const int sp = blockIdx.z;
    const int i0 = blockIdx.x * BM;
    const int tid = threadIdx.x;
    const int w = tid >> 5;
    const int lane = tid & 31;
    const int g4 = lane >> 2;
    const int q4 = lane & 3;

    const int NT = N_SPAT / BN;       // 125
    const int t0 = (sp * NT) / JSPLIT;
    const int t1 = ((sp + 1) * NT) / JSPLIT;

    const float* Qb  = g_Q   + (size_t)b * N_SPAT * DQK;
    const float* Qlb = g_Qlo + (size_t)b * N_SPAT * DQK;
    const float* Kb  = g_K   + (size_t)b * N_SPAT * DQK;
    const float* Klb = g_Klo + (size_t)b * N_SPAT * DQK;
    const float* Vb  = g_V   + (size_t)b * N_SPAT * DV;

    const int r0 = i0 + 16 * w + g4;
    const int r1 = r0 + 8;
    const float ah0 = Qb[r0 * DQK + q4];
    const float ah1 = Qb[r1 * DQK + q4];
    const float ah2 = Qb[r0 * DQK + q4 + 4];
    const float ah3 = Qb[r1 * DQK + q4 + 4];
    const float al0 = Qlb[r0 * DQK + q4];
    const float al1 = Qlb[r1 * DQK + q4];
    const float al2 = Qlb[r0 * DQK + q4 + 4];
    const float al3 = Qlb[r1 * DQK + q4 + 4];

    float m0 = -CUDART_INF_F, m1 = -CUDART_INF_F, l0 = 0.f, l1 = 0.f;
    float o[8][4];
#pragma unroll
    for (int nt = 0; nt < 8; ++nt)
#pragma unroll
        for (int e = 0; e < 4; ++e) o[nt][e] = 0.f;

    const int jj = tid >> 1, hh = tid & 1;

    {
        float4 kh = ((const float4*)(Kb + (size_t)t0 * BN * DQK))[tid];
        float4 kl = ((const float4*)(Klb + (size_t)t0 * BN * DQK))[tid];
        const float* vsrc = Vb + (size_t)t0 * BN * DV;
#pragma unroll
        for (int q = 0; q < 8; ++q) {
            int ch = tid + q * 128;
            int row = ch >> 4, off = ch & 15;
            cp_async16(&sV[0][row * VPAD + off * 4], vsrc + row * 64 + off * 4);
        }
        cp_commit();
        *(float4*)&sKh[0][jj * KPAD + hh * 4] = kh;
        *(float4*)&sKl[0][jj * KPAD + hh * 4] = kl;
        cp_wait0();
        __syncthreads();
    }

    const int srcA = (g4 << 2) + (q4 >> 1);
    const int srcB = srcA + 2;
    const bool oddq = (q4 & 1);

    for (int it = t0; it < t1; ++it) {
        const int cur = (it - t0) & 1;
        const int nxt = cur ^ 1;
        const bool pref = (it + 1 < t1);
        float4 khr, klr;
        if (pref) {
            khr = ((const float4*)(Kb + (size_t)(it + 1) * BN * DQK))[tid];
            klr = ((const float4*)(Klb + (size_t)(it + 1) * BN * DQK))[tid];
            const float* vsrc = Vb + (size_t)(it + 1) * BN * DV;
#pragma unroll
            for (int q = 0; q < 8; ++q) {
                int ch = tid + q * 128;
                int row = ch >> 4, off = ch & 15;
                cp_async16(&sV[nxt][row * VPAD + off * 4], vsrc + row * 64 + off * 4);
            }
            cp_commit();
        }

        float s[8][4];
        {
            const float* kbh = sKh[cur];
            const float* kbl = sKl[cur];
#pragma unroll
            for (int nt = 0; nt < 8; ++nt) {
                float b0h = kbh[(8 * nt + g4) * KPAD + q4];
                float b1h = kbh[(8 * nt + g4) * KPAD + q4 + 4];
                float b0l = kbl[(8 * nt + g4) * KPAD + q4];
                float b1l = kbl[(8 * nt + g4) * KPAD + q4 + 4];
                mma_tf32_z(s[nt], ah0, ah1, ah2, ah3, b0h, b1h);
                mma_tf32 (s[nt], ah0, ah1, ah2, ah3, b0l, b1l);
                mma_tf32 (s[nt], al0, al1, al2, al3, b0h, b1h);
            }
        }

        {
            float mx0 = fmaxf(s[0][0], s[0][1]);
            float mx1 = fmaxf(s[0][2], s[0][3]);
#pragma unroll
            for (int nt = 1; nt < 8; ++nt) {
                mx0 = fmaxf(mx0, fmaxf(s[nt][0], s[nt][1]));
                mx1 = fmaxf(mx1, fmaxf(s[nt][2], s[nt][3]));
            }
            mx0 = fmaxf(mx0, __shfl_xor_sync(0xffffffffu, mx0, 1));
            mx0 = fmaxf(mx0, __shfl_xor_sync(0xffffffffu, mx0, 2));
            mx1 = fmaxf(mx1, __shfl_xor_sync(0xffffffffu, mx1, 1));
            mx1 = fmaxf(mx1, __shfl_xor_sync(0xffffffffu, mx1, 2));
            float m0n = fmaxf(m0, mx0);
            float m1n = fmaxf(m1, mx1);
            float alpha0 = exp2f(m0 - m0n);
            float alpha1 = exp2f(m1 - m1n);
            m0 = m0n; m1 = m1n;
            float rs0 = 0.f, rs1 = 0.f;
#pragma unroll
            for (int nt = 0; nt < 8; ++nt) {
                float p0 = exp2f(s[nt][0] - m0);
                float p1 = exp2f(s[nt][1] - m0);
                float p2 = exp2f(s[nt][2] - m1);
                float p3 = exp2f(s[nt][3] - m1);
                rs0 += p0 + p1;
                rs1 += p2 + p3;
                s[nt][0] = to_tf32(p0); s[nt][1] = to_tf32(p1);
                s[nt][2] = to_tf32(p2); s[nt][3] = to_tf32(p3);
            }
            rs0 += __shfl_xor_sync(0xffffffffu, rs0, 1);
            rs0 += __shfl_xor_sync(0xffffffffu, rs0, 2);
            rs1 += __shfl_xor_sync(0xffffffffu, rs1, 1);
            rs1 += __shfl_xor_sync(0xffffffffu, rs1, 2);
            l0 = l0 * alpha0 + rs0;
            l1 = l1 * alpha1 + rs1;
#pragma unroll
            for (int nt = 0; nt < 8; ++nt) {
                o[nt][0] *= alpha0; o[nt][1] *= alpha0;
                o[nt][2] *= alpha1; o[nt][3] *= alpha1;
            }
        }

        {
            const float* vb = sV[cur];
#pragma unroll
            for (int ks = 0; ks < 8; ++ks) {
                float lo0 = __shfl_sync(0xffffffffu, s[ks][0], srcA);
                float hi0 = __shfl_sync(0xffffffffu, s[ks][1], srcA);
                float a0 = oddq ? hi0 : lo0;
                float lo1 = __shfl_sync(0xffffffffu, s[ks][2], srcA);
                float hi1 = __shfl_sync(0xffffffffu, s[ks][3], srcA);
                float a1 = oddq ? hi1 : lo1;
                float lo2 = __shfl_sync(0xffffffffu, s[ks][0], srcB);
                float hi2 = __shfl_sync(0xffffffffu, s[ks][1], srcB);
                float a2 = oddq ? hi2 : lo2;
                float lo3 = __shfl_sync(0xffffffffu, s[ks][2], srcB);
                float hi3 = __shfl_sync(0xffffffffu, s[ks][3], srcB);
                float a3 = oddq ? hi3 : lo3;
#pragma unroll
                for (int nt = 0; nt < 8; ++nt) {
                    float b0 = vb[(8 * ks + q4) * VPAD + 8 * nt + g4];
                    float b1 = vb[(8 * ks + q4 + 4) * VPAD + 8 * nt + g4];
                    mma_tf32(o[nt], a0, a1, a2, a3, b0, b1);
                }
            }
        }

        if (pref) {
            *(float4*)&sKh[nxt][jj * KPAD + hh * 4] = khr;
            *(float4*)&sKl[nxt][jj * KPAD + hh * 4] = klr;
        }
        cp_wait0();
        __syncthreads();
    }

    const size_t sb = (size_t)(sp * 2 + b);
#pragma unroll
    for (int nt = 0; nt < 8; ++nt) {
        float2* d0 = (float2*)(g_Opart + (sb * N_SPAT + r0) * DV + 8 * nt + 2 * q4);
        *d0 = make_float2(o[nt][0], o[nt][1]);
        float2* d1 = (float2*)(g_Opart + (sb * N_SPAT + r1) * DV + 8 * nt + 2 * q4);
        *d1 = make_float2(o[nt][2], o[nt][3]);
    }
    if (q4 == 0) {
        g_m[sb * N_SPAT + r0] = m0;
        g_m[sb * N_SPAT + r1] = m1;
        g_l[sb * N_SPAT + r0] = l0;
        g_l[sb * N_SPAT + r1] = l1;
    }
}

// =====================================================================
// Merge kernel: combine JSPLIT partials (log-sum-exp, base-2 domain).
// =====================================================================
__global__ __launch_bounds__(256) void merge_kernel(float* __restrict__ out)
{
    __shared__ float T[DV][65];

    const int b = blockIdx.y;
    const int i0 = blockIdx.x * 64;
    const int tid = threadIdx.x;
    const int il = tid >> 2;
    const int cq = tid & 3;
    const int i = i0 + il;

    float mm[JSPLIT], coef[JSPLIT];
    float mstar = -CUDART_INF_F;
#pragma unroll
    for (int s = 0; s < JSPLIT; ++s) {
        mm[s] = g_m[((size_t)(s * 2 + b)) * N_SPAT + i];
        mstar = fmaxf(mstar, mm[s]);
    }
    float denom = 0.f;
#pragma unroll
    for (int s = 0; s < JSPLIT; ++s) {
        coef[s] = exp2f(mm[s] - mstar);
        denom += coef[s] * g_l[((size_t)(s * 2 + b)) * N_SPAT + i];
    }
    const float inv = 1.0f / denom;

    float acc[16];
#pragma unroll
    for (int e = 0; e < 16; ++e) acc[e] = 0.f;
#pragma unroll
    for (int s = 0; s < JSPLIT; ++s) {
        const float4* src = (const float4*)(g_Opart +
            (((size_t)(s * 2 + b)) * N_SPAT + i) * DV + cq * 16);
        float c = coef[s];
#pragma unroll
        for (int q = 0; q < 4; ++q) {
            float4 f = src[q];
            acc[4 * q + 0] = fmaf(c, f.x, acc[4 * q + 0]);
            acc[4 * q + 1] = fmaf(c, f.y, acc[4 * q + 1]);
            acc[4 * q + 2] = fmaf(c, f.z, acc[4 * q + 2]);
            acc[4 * q + 3] = fmaf(c, f.w, acc[4 * q + 3]);
        }
    }
#pragma unroll
    for (int e = 0; e < 16; ++e) T[cq * 16 + e][il] = acc[e] * inv;
    __syncthreads();

    {
        const int c = tid >> 2;
        const int ich = (tid & 3) * 16;
        float* dst = out + ((size_t)b * DV + c) * N_SPAT + i0 + ich;
#pragma unroll
        for (int q = 0; q < 4; ++q)
            ((float4*)dst)[q] = make_float4(T[c][ich + 4 * q + 0], T[c][ich + 4 * q + 1],
                                            T[c][ich + 4 * q + 2], T[c][ich + 4 * q + 3]);
    }
}

// =====================================================================
extern "C" void kernel_launch(void* const* d_in, const int* in_sizes, int n_in,
                              void* d_out, int out_size)
{
    const float* x  = (const float*)d_in[0];
    const float* wq = (const float*)d_in[1];
    const float* bq = (const float*)d_in[2];
    const float* wk = (const float*)d_in[3];
    const float* bk = (const float*)d_in[4];
    const float* wv = (const float*)d_in[5];
    const float* bv = (const float*)d_in[6];
    float* out = (float*)d_out;

    dim3 cgrid(6, 40, 2);                 // group, z*2+yhalf, batch = 480 CTAs
    conv_qkv_kernel<<<cgrid, CONV_T>>>(x, wq, bq, wk, bk, wv, bv);

    dim3 agrid(N_SPAT / BM, 2, JSPLIT);   // 125 x 2 x 2 = 500 CTAs
    attn_kernel<<<agrid, ATT_T>>>();

    dim3 mgrid(N_SPAT / 64, 2);
    merge_kernel<<<mgrid, 256>>>(out);
}

// round 17
// speedup vs baseline: 1.5563x; 1.0527x over previous
#include <cuda_runtime.h>
#include <math_constants.h>

#define N_SPAT 8000
#define CIN 64
#define DQK 8
#define DV 64
#define LOG2E_F 1.4426950408889634f
#define JSPLIT 4

typedef unsigned long long ull;

// ---------------- scratch (no allocations allowed) ----------------
__device__ float g_Q[2 * N_SPAT * DQK];             // hi part (scaled+tf32)
__device__ float g_Qlo[2 * N_SPAT * DQK];           // lo residual (tf32)
__device__ float g_K[2 * N_SPAT * DQK];             // hi part (tf32)
__device__ float g_Klo[2 * N_SPAT * DQK];           // lo residual (tf32)
__device__ float g_V[2 * N_SPAT * DV];              // tf32-rounded
__device__ float g_Opart[JSPLIT * 2 * N_SPAT * DV]; // [s][b][i][c]
__device__ float g_m[JSPLIT * 2 * N_SPAT];
__device__ float g_l[JSPLIT * 2 * N_SPAT];

// ---------------- f32x2 helpers ----------------
__device__ __forceinline__ ull dup2(float x) {
    ull r;
    asm("mov.b64 %0, {%1, %1};" : "=l"(r) : "r"(__float_as_uint(x)));
    return r;
}
__device__ __forceinline__ ull pack2(float lo, float hi) {
    ull r;
    asm("mov.b64 %0, {%1, %2};" : "=l"(r) : "r"(__float_as_uint(lo)), "r"(__float_as_uint(hi)));
    return r;
}
__device__ __forceinline__ void fma2(ull& d, ull a, ull b) {
    asm("fma.rn.f32x2 %0, %1, %2, %0;" : "+l"(d) : "l"(a), "l"(b));
}
__device__ __forceinline__ float lo32(ull v) { return __uint_as_float((unsigned)v); }
__device__ __forceinline__ float hi32(ull v) { return __uint_as_float((unsigned)(v >> 32)); }

// ---------------- tf32 / mma helpers ----------------
__device__ __forceinline__ float to_tf32(float x) {
    unsigned r;
    asm("cvt.rna.tf32.f32 %0, %1;" : "=r"(r) : "f"(x));
    return __uint_as_float(r);
}
__device__ __forceinline__ void mma_tf32(float* c,
    float a0, float a1, float a2, float a3, float b0, float b1)
{
    asm volatile(
        "mma.sync.aligned.m16n8k8.row.col.f32.tf32.tf32.f32 "
        "{%0,%1,%2,%3},{%4,%5,%6,%7},{%8,%9},{%0,%1,%2,%3};"
        : "+f"(c[0]), "+f"(c[1]), "+f"(c[2]), "+f"(c[3])
        : "r"(__float_as_uint(a0)), "r"(__float_as_uint(a1)),
          "r"(__float_as_uint(a2)), "r"(__float_as_uint(a3)),
          "r"(__float_as_uint(b0)), "r"(__float_as_uint(b1)));
}
__device__ __forceinline__ void mma_tf32_z(float* d,
    float a0, float a1, float a2, float a3, float b0, float b1)
{
    asm volatile(
        "mma.sync.aligned.m16n8k8.row.col.f32.tf32.tf32.f32 "
        "{%0,%1,%2,%3},{%4,%5,%6,%7},{%8,%9},{%10,%10,%10,%10};"
        : "=f"(d[0]), "=f"(d[1]), "=f"(d[2]), "=f"(d[3])
        : "r"(__float_as_uint(a0)), "r"(__float_as_uint(a1)),
          "r"(__float_as_uint(a2)), "r"(__float_as_uint(a3)),
          "r"(__float_as_uint(b0)), "r"(__float_as_uint(b1)), "f"(0.f));
}

// ---------------- cp.async helpers ----------------
__device__ __forceinline__ void cp_async16(void* smem, const void* gmem) {
    unsigned saddr = (unsigned)__cvta_generic_to_shared(smem);
    asm volatile("cp.async.cg.shared.global [%0], [%1], 16;\n" :: "r"(saddr), "l"(gmem));
}
__device__ __forceinline__ void cp_commit() { asm volatile("cp.async.commit_group;\n"); }
__device__ __forceinline__ void cp_wait0() { asm volatile("cp.async.wait_group 0;\n"); }

// =====================================================================
// Conv kernel (R16, proven 178us): fused Q/K/V 3x3x3 SAME conv.
// Grid (6 groups, 40 = z*2+yhalf, 2 b) = 480 CTAs, 256 thr, 46.6KB smem.
//   g=0: Q scalar exact + fused log2e + hi/lo split
//   g=1: K scalar exact + fused hi/lo split
//   g=2..5: V (16 oc each) via mma.tf32, fused post-bias tf32
// =====================================================================
#define CONV_T 256
#define SLAB_IC 808
#define WS 24

__global__ __launch_bounds__(CONV_T, 3) void conv_qkv_kernel(
    const float* __restrict__ x,
    const float* __restrict__ wq, const float* __restrict__ bq,
    const float* __restrict__ wk, const float* __restrict__ bk,
    const float* __restrict__ wv, const float* __restrict__ bv)
{
    __shared__ __align__(16) float slab[8 * SLAB_IC];   // 25856 B
    __shared__ __align__(16) float wsm[27 * 8 * WS];    // 20736 B

    const int g = blockIdx.x;
    const int z = blockIdx.y >> 1;
    const int yh = blockIdx.y & 1;
    const int b = blockIdx.z;
    const int tid = threadIdx.x;
    const int w = tid >> 5;
    const int lane = tid & 31;
    const bool tensor = (g >= 2);

    const int yl = (tid < 200) ? tid / 20 : 0;
    const int xc = (tid < 200) ? tid % 20 : 0;
    ull acc[4];
    if (!tensor) {
        const float* bias = (g == 0) ? bq : bk;
#pragma unroll
        for (int p = 0; p < 4; ++p) acc[p] = pack2(bias[2 * p], bias[2 * p + 1]);
    }

    const int g4 = lane >> 2;
    const int q4 = lane & 3;
    const int ntc = (w == 0) ? 4 : 3;     // 25 n-tiles over 8 warps
    float o[4][4];
    int voff[4];
    if (tensor) {
#pragma unroll
        for (int j = 0; j < 4; ++j) {
#pragma unroll
            for (int e = 0; e < 4; ++e) o[j][e] = 0.f;
            int nt = w + 8 * j;
            int v = 8 * nt + g4;
            voff[j] = (nt < 25) ? (v / 20) * 22 + (v % 20) : 0;
        }
    }

    const bool fact = (lane < 22);
    const int fx = lane - 1;
    const bool fxok = ((unsigned)fx < 20u);
    const int wocl = lane & 15, wtp = lane >> 4;

    for (int chunk = 0; chunk < 8; ++chunk) {
        const int icg = chunk * 8 + w;
        __syncthreads();
        // slab fill: warp w fills ic-slot w (div/mod-free)
        {
            const float* xb = x + ((size_t)b * 64 + icg) * 8000;
            float* sl = slab + w * SLAB_IC + lane;
#pragma unroll
            for (int zz = 0; zz < 3; ++zz) {
                int zg = z + zz - 1;
                bool zok = ((unsigned)zg < 20u);
                const float* xz = xb + zg * 400 + fx;
#pragma unroll
                for (int r = 0; r < 12; ++r) {
                    int y = yh * 10 + r - 1;
                    bool ok = fact && fxok && zok && ((unsigned)y < 20u);
                    float v = ok ? xz[y * 20] : 0.f;
                    if (tensor) v = to_tf32(v);
                    if (fact) sl[zz * 264 + r * 22] = v;
                }
            }
        }
        // weight fill: warp w fills ic-slot w
        {
#pragma unroll
            for (int t = 0; t < 14; ++t) {
                int tap = 2 * t + wtp;
                if (tap < 27) {
                    float wv_;
                    if (g == 0)
                        wv_ = (wocl < 8) ? wq[((size_t)wocl * 64 + icg) * 27 + tap] : 0.f;
                    else if (g == 1)
                        wv_ = (wocl < 8) ? wk[((size_t)wocl * 64 + icg) * 27 + tap] : 0.f;
                    else
                        wv_ = to_tf32(wv[((size_t)((g - 2) * 16 + wocl) * 64 + icg) * 27 + tap]);
                    wsm[tap * (8 * WS) + w * WS + wocl] = wv_;
                }
            }
        }
        __syncthreads();

        if (!tensor) {
            if (tid < 200) {
#pragma unroll 2
                for (int ic = 0; ic < 8; ++ic) {
#pragma unroll
                    for (int dz = 0; dz < 3; ++dz) {
                        const float* sl = slab + ic * SLAB_IC + dz * 264 + yl * 22 + xc;
#pragma unroll
                        for (int t9 = 0; t9 < 9; ++t9) {
                            const int off = (t9 / 3) * 22 + (t9 % 3);
                            ull xd = dup2(sl[off]);
                            const ulonglong2* wp = (const ulonglong2*)
                                (wsm + (dz * 9 + t9) * (8 * WS) + ic * WS);
                            ulonglong2 wA = wp[0], wB = wp[1];
                            fma2(acc[0], wA.x, xd);
                            fma2(acc[1], wA.y, xd);
                            fma2(acc[2], wB.x, xd);
                            fma2(acc[3], wB.y, xd);
                        }
                    }
                }
            }
        } else {
#pragma unroll
            for (int dz = 0; dz < 3; ++dz) {
#pragma unroll
                for (int dy = 0; dy < 3; ++dy) {
#pragma unroll
                    for (int dx = 0; dx < 3; ++dx) {
                        const float* wt = wsm + (dz * 9 + dy * 3 + dx) * (8 * WS);
                        float a0 = wt[q4 * WS + g4];
                        float a1 = wt[q4 * WS + g4 + 8];
                        float a2 = wt[(q4 + 4) * WS + g4];
                        float a3 = wt[(q4 + 4) * WS + g4 + 8];
                        const float* bbase = slab + q4 * SLAB_IC + dz * 264 + dy * 22 + dx;
#pragma unroll
                        for (int j = 0; j < 4; ++j) {
                            if (j >= ntc) break;
                            const float* bp = bbase + voff[j];
                            mma_tf32(o[j], a0, a1, a2, a3, bp[0], bp[4 * SLAB_IC]);
                        }
                    }
                }
            }
        }
    }

    // epilogues (rounding fused)
    if (!tensor) {
        if (tid < 200) {
            const bool isQ = (g == 0);
            float* dhi = isQ ? g_Q : g_K;
            float* dlo = isQ ? g_Qlo : g_Klo;
            const float scale = isQ ? LOG2E_F : 1.0f;
            const int i = z * 400 + yh * 200 + tid;
            float hi[8], lo[8];
#pragma unroll
            for (int p = 0; p < 4; ++p) {
                float s0 = lo32(acc[p]) * scale;
                float s1 = hi32(acc[p]) * scale;
                hi[2 * p] = to_tf32(s0);     lo[2 * p] = to_tf32(s0 - hi[2 * p]);
                hi[2 * p + 1] = to_tf32(s1); lo[2 * p + 1] = to_tf32(s1 - hi[2 * p + 1]);
            }
            float4* dh = (float4*)(dhi + ((size_t)b * N_SPAT + i) * DQK);
            dh[0] = make_float4(hi[0], hi[1], hi[2], hi[3]);
            dh[1] = make_float4(hi[4], hi[5], hi[6], hi[7]);
            float4* dl = (float4*)(dlo + ((size_t)b * N_SPAT + i) * DQK);
            dl[0] = make_float4(lo[0], lo[1], lo[2], lo[3]);
            dl[1] = make_float4(lo[4], lo[5], lo[6], lo[7]);
        }
    } else {
        const int oc0 = (g - 2) * 16 + g4;
        const float bias0 = bv[oc0];
        const float bias1 = bv[oc0 + 8];
#pragma unroll
        for (int j = 0; j < 4; ++j) {
            if (j >= ntc) break;
            int nt = w + 8 * j;
            int iv = z * 400 + yh * 200 + 8 * nt + 2 * q4;
            float* d0 = g_V + ((size_t)b * N_SPAT + iv) * DV + oc0;
            float* d1 = g_V + ((size_t)b * N_SPAT + iv + 1) * DV + oc0;
            d0[0] = to_tf32(o[j][0] + bias0);
            d1[0] = to_tf32(o[j][1] + bias0);
            d0[8] = to_tf32(o[j][2] + bias1);
            d1[8] = to_tf32(o[j][3] + bias1);
        }
    }
}

// =====================================================================
// Flash attention (split-KV partials), ALL-mma with 3xTF32 exact QK.
// (R13-R16 proven kernel; JSPLIT now 4 -> 1000 CTAs, ~31 tiles each.)
// =====================================================================
#define BM 64
#define BN 64
#define ATT_T 128
#define KPAD 12
#define VPAD 72

__global__ __launch_bounds__(ATT_T, 4) void attn_kernel()
{
    __shared__ __align__(16) float sKh[2][BN * KPAD];
    __shared__ __align__(16) float sKl[2][BN * KPAD];
    __shared__ __align__(16) float sV[2][BN * VPAD];

    const int b = blockIdx.y;
    const int sp = blockIdx.z;
    const int i0 = blockIdx.x * BM;
    const int tid = threadIdx.x;
    const int w = tid >> 5;
    const int lane = tid & 31;
    const int g4 = lane >> 2;
    const int q4 = lane & 3;

    const int NT = N_SPAT / BN;       // 125
    const int t0 = (sp * NT) / JSPLIT;
    const int t1 = ((sp + 1) * NT) / JSPLIT;

    const float* Qb  = g_Q   + (size_t)b * N_SPAT * DQK;
    const float* Qlb = g_Qlo + (size_t)b * N_SPAT * DQK;
    const float* Kb  = g_K   + (size_t)b * N_SPAT * DQK;
    const float* Klb = g_Klo + (size_t)b * N_SPAT * DQK;
    const float* Vb  = g_V   + (size_t)b * N_SPAT * DV;

    const int r0 = i0 + 16 * w + g4;
    const int r1 = r0 + 8;
    const float ah0 = Qb[r0 * DQK + q4];
    const float ah1 = Qb[r1 * DQK + q4];
    const float ah2 = Qb[r0 * DQK + q4 + 4];
    const float ah3 = Qb[r1 * DQK + q4 + 4];
    const float al0 = Qlb[r0 * DQK + q4];
    const float al1 = Qlb[r1 * DQK + q4];
    const float al2 = Qlb[r0 * DQK + q4 + 4];
    const float al3 = Qlb[r1 * DQK + q4 + 4];

    float m0 = -CUDART_INF_F, m1 = -CUDART_INF_F, l0 = 0.f, l1 = 0.f;
    float o[8][4];
#pragma unroll
    for (int nt = 0; nt < 8; ++nt)
#pragma unroll
        for (int e = 0; e < 4; ++e) o[nt][e] = 0.f;

    const int jj = tid >> 1, hh = tid & 1;

    {
        float4 kh = ((const float4*)(Kb + (size_t)t0 * BN * DQK))[tid];
        float4 kl = ((const float4*)(Klb + (size_t)t0 * BN * DQK))[tid];
        const float* vsrc = Vb + (size_t)t0 * BN * DV;
#pragma unroll
        for (int q = 0; q < 8; ++q) {
            int ch = tid + q * 128;
            int row = ch >> 4, off = ch & 15;
            cp_async16(&sV[0][row * VPAD + off * 4], vsrc + row * 64 + off * 4);
        }
        cp_commit();
        *(float4*)&sKh[0][jj * KPAD + hh * 4] = kh;
        *(float4*)&sKl[0][jj * KPAD + hh * 4] = kl;
        cp_wait0();
        __syncthreads();
    }

    const int srcA = (g4 << 2) + (q4 >> 1);
    const int srcB = srcA + 2;
    const bool oddq = (q4 & 1);

    for (int it = t0; it < t1; ++it) {
        const int cur = (it - t0) & 1;
        const int nxt = cur ^ 1;
        const bool pref = (it + 1 < t1);
        float4 khr, klr;
        if (pref) {
            khr = ((const float4*)(Kb + (size_t)(it + 1) * BN * DQK))[tid];
            klr = ((const float4*)(Klb + (size_t)(it + 1) * BN * DQK))[tid];
            const float* vsrc = Vb + (size_t)(it + 1) * BN * DV;
#pragma unroll
            for (int q = 0; q < 8; ++q) {
                int ch = tid + q * 128;
                int row = ch >> 4, off = ch & 15;
                cp_async16(&sV[nxt][row * VPAD + off * 4], vsrc + row * 64 + off * 4);
            }
            cp_commit();
        }

        float s[8][4];
        {
            const float* kbh = sKh[cur];
            const float* kbl = sKl[cur];
#pragma unroll
            for (int nt = 0; nt < 8; ++nt) {
                float b0h = kbh[(8 * nt + g4) * KPAD + q4];
                float b1h = kbh[(8 * nt + g4) * KPAD + q4 + 4];
                float b0l = kbl[(8 * nt + g4) * KPAD + q4];
                float b1l = kbl[(8 * nt + g4) * KPAD + q4 + 4];
                mma_tf32_z(s[nt], ah0, ah1, ah2, ah3, b0h, b1h);
                mma_tf32 (s[nt], ah0, ah1, ah2, ah3, b0l, b1l);
                mma_tf32 (s[nt], al0, al1, al2, al3, b0h, b1h);
            }
        }

        {
            float mx0 = fmaxf(s[0][0], s[0][1]);
            float mx1 = fmaxf(s[0][2], s[0][3]);
#pragma unroll
            for (int nt = 1; nt < 8; ++nt) {
                mx0 = fmaxf(mx0, fmaxf(s[nt][0], s[nt][1]));
                mx1 = fmaxf(mx1, fmaxf(s[nt][2], s[nt][3]));
            }
            mx0 = fmaxf(mx0, __shfl_xor_sync(0xffffffffu, mx0, 1));
            mx0 = fmaxf(mx0, __shfl_xor_sync(0xffffffffu, mx0, 2));
            mx1 = fmaxf(mx1, __shfl_xor_sync(0xffffffffu, mx1, 1));
            mx1 = fmaxf(mx1, __shfl_xor_sync(0xffffffffu, mx1, 2));
            float m0n = fmaxf(m0, mx0);
            float m1n = fmaxf(m1, mx1);
            float alpha0 = exp2f(m0 - m0n);
            float alpha1 = exp2f(m1 - m1n);
            m0 = m0n; m1 = m1n;
            float rs0 = 0.f, rs1 = 0.f;
#pragma unroll
            for (int nt = 0; nt < 8; ++nt) {
                float p0 = exp2f(s[nt][0] - m0);
                float p1 = exp2f(s[nt][1] - m0);
                float p2 = exp2f(s[nt][2] - m1);
                float p3 = exp2f(s[nt][3] - m1);
                rs0 += p0 + p1;
                rs1 += p2 + p3;
                s[nt][0] = to_tf32(p0); s[nt][1] = to_tf32(p1);
                s[nt][2] = to_tf32(p2); s[nt][3] = to_tf32(p3);
            }
            rs0 += __shfl_xor_sync(0xffffffffu, rs0, 1);
            rs0 += __shfl_xor_sync(0xffffffffu, rs0, 2);
            rs1 += __shfl_xor_sync(0xffffffffu, rs1, 1);
            rs1 += __shfl_xor_sync(0xffffffffu, rs1, 2);
            l0 = l0 * alpha0 + rs0;
            l1 = l1 * alpha1 + rs1;
#pragma unroll
            for (int nt = 0; nt < 8; ++nt) {
                o[nt][0] *= alpha0; o[nt][1] *= alpha0;
                o[nt][2] *= alpha1; o[nt][3] *= alpha1;
            }
        }

        {
            const float* vb = sV[cur];
#pragma unroll
            for (int ks = 0; ks < 8; ++ks) {
                float lo0 = __shfl_sync(0xffffffffu, s[ks][0], srcA);
                float hi0 = __shfl_sync(0xffffffffu, s[ks][1], srcA);
                float a0 = oddq ? hi0 : lo0;
                float lo1 = __shfl_sync(0xffffffffu, s[ks][2], srcA);
                float hi1 = __shfl_sync(0xffffffffu, s[ks][3], srcA);
                float a1 = oddq ? hi1 : lo1;
                float lo2 = __shfl_sync(0xffffffffu, s[ks][0], srcB);
                float hi2 = __shfl_sync(0xffffffffu, s[ks][1], srcB);
                float a2 = oddq ? hi2 : lo2;
                float lo3 = __shfl_sync(0xffffffffu, s[ks][2], srcB);
                float hi3 = __shfl_sync(0xffffffffu, s[ks][3], srcB);
                float a3 = oddq ? hi3 : lo3;
#pragma unroll
                for (int nt = 0; nt < 8; ++nt) {
                    float b0 = vb[(8 * ks + q4) * VPAD + 8 * nt + g4];
                    float b1 = vb[(8 * ks + q4 + 4) * VPAD + 8 * nt + g4];
                    mma_tf32(o[nt], a0, a1, a2, a3, b0, b1);
                }
            }
        }

        if (pref) {
            *(float4*)&sKh[nxt][jj * KPAD + hh * 4] = khr;
            *(float4*)&sKl[nxt][jj * KPAD + hh * 4] = klr;
        }
        cp_wait0();
        __syncthreads();
    }

    const size_t sb = (size_t)(sp * 2 + b);
#pragma unroll
    for (int nt = 0; nt < 8; ++nt) {
        float2* d0 = (float2*)(g_Opart + (sb * N_SPAT + r0) * DV + 8 * nt + 2 * q4);
        *d0 = make_float2(o[nt][0], o[nt][1]);
        float2* d1 = (float2*)(g_Opart + (sb * N_SPAT + r1) * DV + 8 * nt + 2 * q4);
        *d1 = make_float2(o[nt][2], o[nt][3]);
    }
    if (q4 == 0) {
        g_m[sb * N_SPAT + r0] = m0;
        g_m[sb * N_SPAT + r1] = m1;
        g_l[sb * N_SPAT + r0] = l0;
        g_l[sb * N_SPAT + r1] = l1;
    }
}

// =====================================================================
// Merge kernel: combine JSPLIT partials (log-sum-exp, base-2 domain).
// =====================================================================
__global__ __launch_bounds__(256) void merge_kernel(float* __restrict__ out)
{
    __shared__ float T[DV][65];

    const int b = blockIdx.y;
    const int i0 = blockIdx.x * 64;
    const int tid = threadIdx.x;
    const int il = tid >> 2;
    const int cq = tid & 3;
    const int i = i0 + il;

    float mm[JSPLIT], coef[JSPLIT];
    float mstar = -CUDART_INF_F;
#pragma unroll
    for (int s = 0; s < JSPLIT; ++s) {
        mm[s] = g_m[((size_t)(s * 2 + b)) * N_SPAT + i];
        mstar = fmaxf(mstar, mm[s]);
    }
    float denom = 0.f;
#pragma unroll
    for (int s = 0; s < JSPLIT; ++s) {
        coef[s] = exp2f(mm[s] - mstar);
        denom += coef[s] * g_l[((size_t)(s * 2 + b)) * N_SPAT + i];
    }
    const float inv = 1.0f / denom;

    float acc[16];
#pragma unroll
    for (int e = 0; e < 16; ++e) acc[e] = 0.f;
#pragma unroll
    for (int s = 0; s < JSPLIT; ++s) {
        const float4* src = (const float4*)(g_Opart +
            (((size_t)(s * 2 + b)) * N_SPAT + i) * DV + cq * 16);
        float c = coef[s];
#pragma unroll
        for (int q = 0; q < 4; ++q) {
            float4 f = src[q];
            acc[4 * q + 0] = fmaf(c, f.x, acc[4 * q + 0]);
            acc[4 * q + 1] = fmaf(c, f.y, acc[4 * q + 1]);
            acc[4 * q + 2] = fmaf(c, f.z, acc[4 * q + 2]);
            acc[4 * q + 3] = fmaf(c, f.w, acc[4 * q + 3]);
        }
    }
#pragma unroll
    for (int e = 0; e < 16; ++e) T[cq * 16 + e][il] = acc[e] * inv;
    __syncthreads();

    {
        const int c = tid >> 2;
        const int ich = (tid & 3) * 16;
        float* dst = out + ((size_t)b * DV + c) * N_SPAT + i0 + ich;
#pragma unroll
        for (int q = 0; q < 4; ++q)
            ((float4*)dst)[q] = make_float4(T[c][ich + 4 * q + 0], T[c][ich + 4 * q + 1],
                                            T[c][ich + 4 * q + 2], T[c][ich + 4 * q + 3]);
    }
}

// =====================================================================
extern "C" void kernel_launch(void* const* d_in, const int* in_sizes, int n_in,
                              void* d_out, int out_size)
{
    const float* x  = (const float*)d_in[0];
    const float* wq = (const float*)d_in[1];
    const float* bq = (const float*)d_in[2];
    const float* wk = (const float*)d_in[3];
    const float* bk = (const float*)d_in[4];
    const float* wv = (const float*)d_in[5];
    const float* bv = (const float*)d_in[6];
    float* out = (float*)d_out;

    dim3 cgrid(6, 40, 2);                 // group, z*2+yhalf, batch = 480 CTAs
    conv_qkv_kernel<<<cgrid, CONV_T>>>(x, wq, bq, wk, bk, wv, bv);

    dim3 agrid(N_SPAT / BM, 2, JSPLIT);   // 125 x 2 x 4 = 1000 CTAs
    attn_kernel<<<agrid, ATT_T>>>();

    dim3 mgrid(N_SPAT / 64, 2);
    merge_kernel<<<mgrid, 256>>>(out);
}